// round 12
// baseline (speedup 1.0000x reference)
#include <cuda_runtime.h>
#include <math.h>

#define NI 80000
#define NU 20000
#define NN 100000
#define EE 1000000
#define NB_P 391   // ceil(NN/256) blocks for the fused preprocessing kernel

// ---------------- scratch (static device globals; no allocs) ----------------
__device__ float g_x[NN * 64];
__device__ float g_xw[NN * 64];
__device__ float g_h[NN * 64];
__device__ float g_xhat[NN * 64];
__device__ float g_xcur[NN * 64];
__device__ int   g_cnt[NN];
__device__ int   g_deg[NN];
__device__ int   g_start[NN + 1];
__device__ int   g_cursor[NN];
__device__ int   g_csr[EE];
__device__ float g_dinv[NN];
__device__ int   g_bsum[512];
__device__ int   g_boff[512];
__device__ unsigned g_gb_cnt = 0;   // monotonic grid-barrier arrive counter
__device__ unsigned g_gb_flag = 0;  // monotonic grid-barrier release counter

__device__ __forceinline__ float leaky(float v) { return v >= 0.f ? v : 0.01f * v; }

__device__ __forceinline__ unsigned long long packdup(float a) {
    unsigned long long r;
    asm("mov.b64 %0, {%1, %1};" : "=l"(r) : "f"(a));
    return r;
}
__device__ __forceinline__ void ffma2(unsigned long long& d, unsigned long long a,
                                      unsigned long long b) {
    asm("fma.rn.f32x2 %0, %1, %2, %0;" : "+l"(d) : "l"(a), "l"(b));
}
__device__ __forceinline__ float2 unpack2(unsigned long long v) {
    float2 f;
    asm("mov.b64 {%0, %1}, %2;" : "=f"(f.x), "=f"(f.y) : "l"(v));
    return f;
}

// Grid barrier: monotonic epochs, safe across graph replays.
// basef is the flag value sampled at kernel entry (stable: flag only moves
// after ALL blocks arrive at barrier 1, and every block samples first).
// Last arriver detected via (t+1) % nb == 0 on the monotonic arrive counter.
__device__ __forceinline__ void grid_bar(unsigned basef, int k, int nb) {
    __syncthreads();
    if (threadIdx.x == 0) {
        __threadfence();
        unsigned t = atomicAdd(&g_gb_cnt, 1u);
        if ((t + 1u) % (unsigned)nb == 0u) {
            atomicAdd(&g_gb_flag, 1u);
        } else {
            while ((int)(*(volatile unsigned*)&g_gb_flag - basef) < k) { }
        }
        __threadfence();
    }
    __syncthreads();
}

// ---------------- build x (items + users) + zero counters, one launch ----------
#define ITEM_B (NI / 8)
#define USER_B 592
__global__ void __launch_bounds__(256) k_build(const float* __restrict__ f,
                                               const float* __restrict__ uf,
                                               const float* __restrict__ Wu,
                                               const float* __restrict__ bu) {
    __shared__ __align__(16) float ws[128 * 64];
    int tid = threadIdx.x;
    int zi = blockIdx.x * 256 + tid;
    if (zi < NN) { g_cnt[zi] = 0; g_deg[zi] = 0; }

    if (blockIdx.x < ITEM_B) {
        int w = blockIdx.x * 8 + (tid >> 5);
        int lane = tid & 31;
        float2 v = *reinterpret_cast<const float2*>(f + (size_t)w * 64 + 2 * lane);
        float ss = v.x * v.x + v.y * v.y;
        ss += __shfl_xor_sync(0xffffffffu, ss, 16);
        ss += __shfl_xor_sync(0xffffffffu, ss, 8);
        ss += __shfl_xor_sync(0xffffffffu, ss, 4);
        ss += __shfl_xor_sync(0xffffffffu, ss, 2);
        ss += __shfl_xor_sync(0xffffffffu, ss, 1);
        float sc = __fdividef(1.f, fmaxf(sqrtf(ss), 1e-12f));
        *reinterpret_cast<float2*>(g_x + (size_t)w * 64 + 2 * lane) =
            make_float2(v.x * sc, v.y * sc);
        return;
    }
    int ub = blockIdx.x - ITEM_B;
    for (int i = tid; i < 8192; i += 256) {
        int c = i >> 7, k = i & 127;
        ws[k * 64 + c] = Wu[i];
    }
    __syncthreads();
    int lane = tid & 31, wp = tid >> 5;
    for (int u = ub * 8 + wp; u < NU; u += USER_B * 8) {
        float4 my = *reinterpret_cast<const float4*>(uf + (size_t)u * 128 + lane * 4);
        float a0 = bu[2 * lane], a1 = bu[2 * lane + 1];
        for (int sl = 0; sl < 32; sl++) {
            float v0 = __shfl_sync(0xffffffffu, my.x, sl);
            float v1 = __shfl_sync(0xffffffffu, my.y, sl);
            float v2 = __shfl_sync(0xffffffffu, my.z, sl);
            float v3 = __shfl_sync(0xffffffffu, my.w, sl);
            int k0 = sl * 4;
            float2 w;
            w = *reinterpret_cast<const float2*>(&ws[(k0 + 0) * 64 + 2 * lane]);
            a0 = fmaf(v0, w.x, a0); a1 = fmaf(v0, w.y, a1);
            w = *reinterpret_cast<const float2*>(&ws[(k0 + 1) * 64 + 2 * lane]);
            a0 = fmaf(v1, w.x, a0); a1 = fmaf(v1, w.y, a1);
            w = *reinterpret_cast<const float2*>(&ws[(k0 + 2) * 64 + 2 * lane]);
            a0 = fmaf(v2, w.x, a0); a1 = fmaf(v2, w.y, a1);
            w = *reinterpret_cast<const float2*>(&ws[(k0 + 3) * 64 + 2 * lane]);
            a0 = fmaf(v3, w.x, a0); a1 = fmaf(v3, w.y, a1);
        }
        float t0 = tanhf(a0), t1 = tanhf(a1);
        float ss = t0 * t0 + t1 * t1;
        ss += __shfl_xor_sync(0xffffffffu, ss, 16);
        ss += __shfl_xor_sync(0xffffffffu, ss, 8);
        ss += __shfl_xor_sync(0xffffffffu, ss, 4);
        ss += __shfl_xor_sync(0xffffffffu, ss, 2);
        ss += __shfl_xor_sync(0xffffffffu, ss, 1);
        float sc = __fdividef(1.f, fmaxf(sqrtf(ss), 1e-12f));
        *reinterpret_cast<float2*>(g_x + (size_t)(NI + u) * 64 + 2 * lane) =
            make_float2(t0 * sc, t1 * sc);
    }
}

// -------- fused preprocessing: hist -> scan -> prep -> scatter, ONE kernel --------
__global__ void __launch_bounds__(256) k_prep(const int* __restrict__ src,
                                              const int* __restrict__ dst, int E) {
    __shared__ int sd[256];
    __shared__ int s2[512];
    int tid = threadIdx.x;
    int bid = blockIdx.x;
    unsigned basef = *(volatile unsigned*)&g_gb_flag;

    // phase 1: degree histograms
    for (int i = bid * 256 + tid; i < E; i += NB_P * 256) {
        atomicAdd(&g_cnt[dst[i]], 1);
        atomicAdd(&g_deg[src[i]], 1);
    }
    grid_bar(basef, 1, NB_P);

    // phase 2: block-local inclusive scan of g_cnt
    int idx = bid * 256 + tid;
    int v = (idx < NN) ? g_cnt[idx] : 0;
    sd[tid] = v;
    __syncthreads();
    for (int off = 1; off < 256; off <<= 1) {
        int add = (tid >= off) ? sd[tid - off] : 0;
        __syncthreads();
        sd[tid] += add;
        __syncthreads();
    }
    int incl = sd[tid];
    if (idx < NN) g_start[idx + 1] = incl;
    if (tid == 255) g_bsum[bid] = incl;
    grid_bar(basef, 2, NB_P);

    // phase 3: block 0 scans the 391 block sums (two 256-wide scans + splice)
    if (bid == 0) {
        int vlo = (tid < NB_P) ? g_bsum[tid] : 0;
        int vhi = (tid + 256 < NB_P) ? g_bsum[tid + 256] : 0;
        s2[tid] = vlo;
        s2[tid + 256] = vhi;
        __syncthreads();
        for (int off = 1; off < 256; off <<= 1) {
            int alo = (tid >= off) ? s2[tid - off] : 0;
            int ahi = (tid >= off) ? s2[256 + tid - off] : 0;
            __syncthreads();
            s2[tid] += alo;
            s2[256 + tid] += ahi;
            __syncthreads();
        }
        int lowtot = s2[255];
        // exclusive offsets
        if (tid < NB_P) g_boff[tid] = s2[tid] - vlo;
        if (tid + 256 < NB_P) g_boff[tid + 256] = lowtot + s2[tid + 256] - vhi;
    }
    grid_bar(basef, 3, NB_P);

    // phase 4: apply offsets + init cursors + dinv
    if (idx < NN) {
        int val = g_start[idx + 1] + g_boff[bid];
        g_start[idx + 1] = val;
        if (idx + 1 < NN) g_cursor[idx + 1] = val;
        int d = g_deg[idx];
        g_dinv[idx] = (d > 0) ? rsqrtf((float)d) : 0.f;
    }
    if (idx == 0) { g_start[0] = 0; g_cursor[0] = 0; }
    grid_bar(basef, 4, NB_P);

    // phase 5: CSR scatter
    for (int i = bid * 256 + tid; i < E; i += NB_P * 256) {
        int d = dst[i];
        int p = atomicAdd(&g_cursor[d], 1);
        g_csr[p] = src[i];
    }
}

// ======================= GEMM core (R9: 8 rows x 8 cols / thread, 128 thr) ==========
struct Acc8x4 { unsigned long long a[8][4]; };

__device__ __forceinline__ void gemm_pass(const float* __restrict__ xs,
                                          const float* __restrict__ ws,
                                          int rg, int c0, int swz, Acc8x4& A) {
#pragma unroll
    for (int rr = 0; rr < 8; rr++)
#pragma unroll
        for (int p = 0; p < 4; p++) A.a[rr][p] = 0ull;
#pragma unroll 4
    for (int kb = 0; kb < 64; kb += 4) {
        float4 a4[8];
#pragma unroll
        for (int rr = 0; rr < 8; rr++)
            a4[rr] = *(const float4*)&xs[(rg * 8 + rr) * 64 + (kb ^ swz)];
#pragma unroll
        for (int j = 0; j < 4; j++) {
            int k = kb + j;
            ulonglong2 wA = *(const ulonglong2*)&ws[k * 64 + c0];
            ulonglong2 wB = *(const ulonglong2*)&ws[k * 64 + c0 + 4];
#pragma unroll
            for (int rr = 0; rr < 8; rr++) {
                float a = (j == 0) ? a4[rr].x : (j == 1) ? a4[rr].y
                          : (j == 2) ? a4[rr].z : a4[rr].w;
                unsigned long long aa = packdup(a);
                ffma2(A.a[rr][0], aa, wA.x); ffma2(A.a[rr][1], aa, wA.y);
                ffma2(A.a[rr][2], aa, wB.x); ffma2(A.a[rr][3], aa, wB.y);
            }
        }
    }
}

__device__ __forceinline__ void load_xs(float* __restrict__ xs,
                                        const float* __restrict__ in,
                                        int row0, int n, int tid) {
    for (int i = tid * 4; i < 8192; i += 512) {
        int r = i >> 6, k = i & 63;
        int sw = ((r >> 3) & 7) * 8;
        int gr = row0 + r;
        float4 v = (gr < n) ? *(const float4*)(in + (size_t)gr * 64 + k)
                            : make_float4(0.f, 0.f, 0.f, 0.f);
        *(float4*)&xs[r * 64 + (k ^ sw)] = v;
    }
}

// ---------------- fused dual GEMM, two passes, reloaded weight buffer ----------
__global__ void __launch_bounds__(128, 4) k_dual(const float* __restrict__ in,
                                                 const float* __restrict__ Wg,
                                                 const float* __restrict__ Wl,
                                                 const float* __restrict__ bias,
                                                 const float* __restrict__ idw,
                                                 float* __restrict__ xw,
                                                 float* __restrict__ xhat, int n) {
    __shared__ __align__(16) float ws[4096];
    __shared__ __align__(16) float xs[8192];
    int tid = threadIdx.x;
    int rg = tid >> 3;
    int cg = tid & 7;
    int c0 = cg * 8;
    int swz = (rg & 7) * 8;
    int row0 = blockIdx.x * 128;

    for (int i = tid; i < 4096; i += 128) ws[i] = Wg[i];
    load_xs(xs, in, row0, n, tid);
    __syncthreads();

    Acc8x4 A;
    gemm_pass(xs, ws, rg, c0, swz, A);
#pragma unroll
    for (int rr = 0; rr < 8; rr++) {
        int r = row0 + rg * 8 + rr;
        if (r < n) {
            size_t base = (size_t)r * 64 + c0;
            float2 v0 = unpack2(A.a[rr][0]), v1 = unpack2(A.a[rr][1]);
            float2 v2 = unpack2(A.a[rr][2]), v3 = unpack2(A.a[rr][3]);
            *(float4*)(xw + base) = make_float4(v0.x, v0.y, v1.x, v1.y);
            *(float4*)(xw + base + 4) = make_float4(v2.x, v2.y, v3.x, v3.y);
        }
    }
    __syncthreads();

    for (int i = tid; i < 4096; i += 128) {
        int k = i >> 6, c = i & 63;
        ws[i] = Wl[c * 64 + k];
    }
    __syncthreads();

    gemm_pass(xs, ws, rg, c0, swz, A);
    float4 b0 = *(const float4*)(bias + c0);
    float4 b1 = *(const float4*)(bias + c0 + 4);
#pragma unroll
    for (int rr = 0; rr < 8; rr++) {
        int r = row0 + rg * 8 + rr;
        if (r < n) {
            size_t base = (size_t)r * 64 + c0;
            float2 u0 = unpack2(A.a[rr][0]), u1 = unpack2(A.a[rr][1]);
            float2 u2 = unpack2(A.a[rr][2]), u3 = unpack2(A.a[rr][3]);
            float4 i0 = *(const float4*)(idw + base);
            float4 i1 = *(const float4*)(idw + base + 4);
            *(float4*)(xhat + base) = make_float4(
                leaky(u0.x + b0.x) + i0.x, leaky(u0.y + b0.y) + i0.y,
                leaky(u1.x + b0.z) + i0.z, leaky(u1.y + b0.w) + i0.w);
            *(float4*)(xhat + base + 4) = make_float4(
                leaky(u2.x + b1.x) + i1.x, leaky(u2.y + b1.y) + i1.y,
                leaky(u3.x + b1.z) + i1.z, leaky(u3.y + b1.w) + i1.w);
        }
    }
}

// ---------------- final GEMM: v = leaky(h@W' + b + xhat); write outb & out2 --------
__global__ void __launch_bounds__(128, 4) k_final(const float* __restrict__ in,
                                                  const float* __restrict__ W,
                                                  const float* __restrict__ bias,
                                                  const float* __restrict__ add,
                                                  float* __restrict__ outb,
                                                  float* __restrict__ out2, int n) {
    __shared__ __align__(16) float ws[4096];
    __shared__ __align__(16) float xs[8192];
    int tid = threadIdx.x;
    int rg = tid >> 3, cg = tid & 7;
    int c0 = cg * 8;
    int swz = (rg & 7) * 8;
    int row0 = blockIdx.x * 128;

    for (int i = tid; i < 4096; i += 128) {
        int k = i >> 6, c = i & 63;
        ws[i] = W[c * 64 + k];
    }
    load_xs(xs, in, row0, n, tid);
    __syncthreads();

    Acc8x4 A;
    gemm_pass(xs, ws, rg, c0, swz, A);
    float4 b0 = *(const float4*)(bias + c0);
    float4 b1 = *(const float4*)(bias + c0 + 4);
#pragma unroll
    for (int rr = 0; rr < 8; rr++) {
        int r = row0 + rg * 8 + rr;
        if (r < n) {
            size_t base = (size_t)r * 64 + c0;
            float2 u0 = unpack2(A.a[rr][0]), u1 = unpack2(A.a[rr][1]);
            float2 u2 = unpack2(A.a[rr][2]), u3 = unpack2(A.a[rr][3]);
            float4 h0 = *(const float4*)(add + base);
            float4 h1 = *(const float4*)(add + base + 4);
            float4 o0 = make_float4(leaky(u0.x + b0.x + h0.x), leaky(u0.y + b0.y + h0.y),
                                    leaky(u1.x + b0.z + h0.z), leaky(u1.y + b0.w + h0.w));
            float4 o1 = make_float4(leaky(u2.x + b1.x + h1.x), leaky(u2.y + b1.y + h1.y),
                                    leaky(u3.x + b1.z + h1.z), leaky(u3.y + b1.w + h1.w));
            *(float4*)(outb + base) = o0;
            *(float4*)(outb + base + 4) = o1;
            *(float4*)(out2 + (size_t)r * 128 + c0) = o0;
            *(float4*)(out2 + (size_t)r * 128 + c0 + 4) = o1;
        }
    }
}

// ---------------- GAT aggregation (R9): warp per dst node, 4-edge online softmax ----
__global__ void __launch_bounds__(256) k_agg() {
    int w = (blockIdx.x * blockDim.x + threadIdx.x) >> 5;
    int lane = threadIdx.x & 31;
    if (w >= NN) return;
    int s = g_start[w], e = g_start[w + 1];
    int cnt = e - s;
    float2 xv = *reinterpret_cast<const float2*>(g_xw + (size_t)w * 64 + 2 * lane);
    const float NEGINF = __int_as_float(0xff800000);
    float m = NEGINF, z = 0.f;
    float2 acc = make_float2(0.f, 0.f);
    int u_l = 0; float dv_l = 0.f;
    if (lane < cnt) { u_l = g_csr[s + lane]; dv_l = g_dinv[u_l]; }
    for (int i = 0; i < cnt; i += 4) {
        int j = i & 31;
        if (j == 0 && i > 0) {
            int idx = s + i + lane;
            u_l = (idx < e) ? g_csr[idx] : 0;
            dv_l = (idx < e) ? g_dinv[u_l] : 0.f;
        }
        int u0 = __shfl_sync(0xffffffffu, u_l, j);
        int u1 = __shfl_sync(0xffffffffu, u_l, j + 1);
        int u2 = __shfl_sync(0xffffffffu, u_l, j + 2);
        int u3 = __shfl_sync(0xffffffffu, u_l, j + 3);
        float dv0 = __shfl_sync(0xffffffffu, dv_l, j);
        float dv1 = __shfl_sync(0xffffffffu, dv_l, j + 1);
        float dv2 = __shfl_sync(0xffffffffu, dv_l, j + 2);
        float dv3 = __shfl_sync(0xffffffffu, dv_l, j + 3);
        float2 a0 = *reinterpret_cast<const float2*>(g_xw + (size_t)u0 * 64 + 2 * lane);
        float2 a1 = *reinterpret_cast<const float2*>(g_xw + (size_t)u1 * 64 + 2 * lane);
        float2 a2 = *reinterpret_cast<const float2*>(g_xw + (size_t)u2 * 64 + 2 * lane);
        float2 a3 = *reinterpret_cast<const float2*>(g_xw + (size_t)u3 * 64 + 2 * lane);
        float p0 = fmaf(xv.x, a0.x, xv.y * a0.y);
        float p1 = fmaf(xv.x, a1.x, xv.y * a1.y);
        float p2 = fmaf(xv.x, a2.x, xv.y * a2.y);
        float p3 = fmaf(xv.x, a3.x, xv.y * a3.y);
#pragma unroll
        for (int o = 16; o; o >>= 1) {
            p0 += __shfl_xor_sync(0xffffffffu, p0, o);
            p1 += __shfl_xor_sync(0xffffffffu, p1, o);
            p2 += __shfl_xor_sync(0xffffffffu, p2, o);
            p3 += __shfl_xor_sync(0xffffffffu, p3, o);
        }
        float lg0 = p0 * __fdividef(1.f, 1.f + __expf(-p0 * dv0));
        float lg1 = (i + 1 < cnt) ? p1 * __fdividef(1.f, 1.f + __expf(-p1 * dv1)) : NEGINF;
        float lg2 = (i + 2 < cnt) ? p2 * __fdividef(1.f, 1.f + __expf(-p2 * dv2)) : NEGINF;
        float lg3 = (i + 3 < cnt) ? p3 * __fdividef(1.f, 1.f + __expf(-p3 * dv3)) : NEGINF;
        float nm = fmaxf(fmaxf(m, lg0), fmaxf(fmaxf(lg1, lg2), lg3));
        float scl = __expf(m - nm);
        float pe0 = __expf(lg0 - nm);
        float pe1 = __expf(lg1 - nm);
        float pe2 = __expf(lg2 - nm);
        float pe3 = __expf(lg3 - nm);
        z = z * scl + ((pe0 + pe1) + (pe2 + pe3));
        acc.x = fmaf(acc.x, scl,
                     fmaf(pe0, a0.x, fmaf(pe1, a1.x, fmaf(pe2, a2.x, pe3 * a3.x))));
        acc.y = fmaf(acc.y, scl,
                     fmaf(pe0, a0.y, fmaf(pe1, a1.y, fmaf(pe2, a2.y, pe3 * a3.y))));
        m = nm;
    }
    float inv = __fdividef(1.f, z + 1e-16f);
    *reinterpret_cast<float2*>(g_h + (size_t)w * 64 + 2 * lane) =
        make_float2(leaky(acc.x * inv), leaky(acc.y * inv));
}

// ---------------- launch ----------------
extern "C" void kernel_launch(void* const* d_in, const int* in_sizes, int n_in,
                              void* d_out, int out_size) {
    const float* features = (const float*)d_in[0];
    const float* user_features = (const float*)d_in[1];
    const float* id_emb = (const float*)d_in[2];
    const float* user_mlp_w = (const float*)d_in[3];
    const float* user_mlp_b = (const float*)d_in[4];
    const float* gat1_w = (const float*)d_in[5];
    const float* lin1_w = (const float*)d_in[6];
    const float* lin1_b = (const float*)d_in[7];
    const float* g1_w = (const float*)d_in[8];
    const float* g1_b = (const float*)d_in[9];
    const float* gat2_w = (const float*)d_in[10];
    const float* lin2_w = (const float*)d_in[11];
    const float* lin2_b = (const float*)d_in[12];
    const float* g2_w = (const float*)d_in[13];
    const float* g2_b = (const float*)d_in[14];
    const int* edge_index = (const int*)d_in[15];
    float* out = (float*)d_out;

    int E = in_sizes[15] / 2;
    if (E > EE) E = EE;
    const int* src = edge_index;
    const int* dst = edge_index + E;

    float *p_x, *p_xw, *p_h, *p_xhat, *p_xcur;
    cudaGetSymbolAddress((void**)&p_x, g_x);
    cudaGetSymbolAddress((void**)&p_xw, g_xw);
    cudaGetSymbolAddress((void**)&p_h, g_h);
    cudaGetSymbolAddress((void**)&p_xhat, g_xhat);
    cudaGetSymbolAddress((void**)&p_xcur, g_xcur);

    const int GT = (NN + 127) / 128;  // 782 gemm tiles

    // 1: build x (items+users) + zero counters
    k_build<<<ITEM_B + USER_B, 256>>>(features, user_features, user_mlp_w, user_mlp_b);
    // 2: fused CSR preprocessing (hist -> scan -> prep -> scatter), grid-synced
    k_prep<<<NB_P, 256>>>(src, dst, E);
    // 3: hop-1 dual GEMM
    k_dual<<<GT, 128>>>(p_x, gat1_w, lin1_w, lin1_b, id_emb, p_xw, p_xhat, NN);
    // 4: hop-1 aggregation  (ncu profiles this slot)
    k_agg<<<(NN + 7) / 8, 256>>>();
    // 5: hop-1 final
    k_final<<<GT, 128>>>(p_h, g1_w, g1_b, p_xhat, p_xcur, out, NN);
    // 6-8: hop 2
    k_dual<<<GT, 128>>>(p_xcur, gat2_w, lin2_w, lin2_b, id_emb, p_xw, p_xhat, NN);
    k_agg<<<(NN + 7) / 8, 256>>>();
    k_final<<<GT, 128>>>(p_h, g2_w, g2_b, p_xhat, p_x, out + 64, NN);
}

// round 13
// speedup vs baseline: 1.0645x; 1.0645x over previous
#include <cuda_runtime.h>
#include <math.h>

#define NI 80000
#define NU 20000
#define NN 100000
#define EE 1000000

// ---------------- scratch (static device globals; no allocs) ----------------
__device__ float g_x[NN * 64];
__device__ float g_xw[NN * 64];
__device__ float g_h[NN * 64];
__device__ float g_xhat[NN * 64];
__device__ float g_xcur[NN * 64];
__device__ int   g_cnt[NN];
__device__ int   g_deg[NN];
__device__ int   g_start[NN + 1];
__device__ int   g_cursor[NN];
__device__ int   g_csr[EE];
__device__ float g_dinv[NN];
__device__ int   g_bsum[128];

__device__ __forceinline__ float leaky(float v) { return v >= 0.f ? v : 0.01f * v; }

__device__ __forceinline__ unsigned long long packdup(float a) {
    unsigned long long r;
    asm("mov.b64 %0, {%1, %1};" : "=l"(r) : "f"(a));
    return r;
}
__device__ __forceinline__ void ffma2(unsigned long long& d, unsigned long long a,
                                      unsigned long long b) {
    asm("fma.rn.f32x2 %0, %1, %2, %0;" : "+l"(d) : "l"(a), "l"(b));
}
__device__ __forceinline__ float2 unpack2(unsigned long long v) {
    float2 f;
    asm("mov.b64 {%0, %1}, %2;" : "=f"(f.x), "=f"(f.y) : "l"(v));
    return f;
}

// ---------------- build x (items + users) + zero counters, one launch ----------
#define ITEM_B (NI / 8)
#define USER_B 592
__global__ void __launch_bounds__(256) k_build(const float* __restrict__ f,
                                               const float* __restrict__ uf,
                                               const float* __restrict__ Wu,
                                               const float* __restrict__ bu) {
    __shared__ __align__(16) float ws[128 * 64];
    int tid = threadIdx.x;
    int zi = blockIdx.x * 256 + tid;
    if (zi < NN) { g_cnt[zi] = 0; g_deg[zi] = 0; }

    if (blockIdx.x < ITEM_B) {
        int w = blockIdx.x * 8 + (tid >> 5);
        int lane = tid & 31;
        float2 v = *reinterpret_cast<const float2*>(f + (size_t)w * 64 + 2 * lane);
        float ss = v.x * v.x + v.y * v.y;
        ss += __shfl_xor_sync(0xffffffffu, ss, 16);
        ss += __shfl_xor_sync(0xffffffffu, ss, 8);
        ss += __shfl_xor_sync(0xffffffffu, ss, 4);
        ss += __shfl_xor_sync(0xffffffffu, ss, 2);
        ss += __shfl_xor_sync(0xffffffffu, ss, 1);
        float sc = __fdividef(1.f, fmaxf(sqrtf(ss), 1e-12f));
        *reinterpret_cast<float2*>(g_x + (size_t)w * 64 + 2 * lane) =
            make_float2(v.x * sc, v.y * sc);
        return;
    }
    int ub = blockIdx.x - ITEM_B;
    for (int i = tid; i < 8192; i += 256) {
        int c = i >> 7, k = i & 127;
        ws[k * 64 + c] = Wu[i];
    }
    __syncthreads();
    int lane = tid & 31, wp = tid >> 5;
    for (int u = ub * 8 + wp; u < NU; u += USER_B * 8) {
        float4 my = *reinterpret_cast<const float4*>(uf + (size_t)u * 128 + lane * 4);
        float a0 = bu[2 * lane], a1 = bu[2 * lane + 1];
        for (int sl = 0; sl < 32; sl++) {
            float v0 = __shfl_sync(0xffffffffu, my.x, sl);
            float v1 = __shfl_sync(0xffffffffu, my.y, sl);
            float v2 = __shfl_sync(0xffffffffu, my.z, sl);
            float v3 = __shfl_sync(0xffffffffu, my.w, sl);
            int k0 = sl * 4;
            float2 w;
            w = *reinterpret_cast<const float2*>(&ws[(k0 + 0) * 64 + 2 * lane]);
            a0 = fmaf(v0, w.x, a0); a1 = fmaf(v0, w.y, a1);
            w = *reinterpret_cast<const float2*>(&ws[(k0 + 1) * 64 + 2 * lane]);
            a0 = fmaf(v1, w.x, a0); a1 = fmaf(v1, w.y, a1);
            w = *reinterpret_cast<const float2*>(&ws[(k0 + 2) * 64 + 2 * lane]);
            a0 = fmaf(v2, w.x, a0); a1 = fmaf(v2, w.y, a1);
            w = *reinterpret_cast<const float2*>(&ws[(k0 + 3) * 64 + 2 * lane]);
            a0 = fmaf(v3, w.x, a0); a1 = fmaf(v3, w.y, a1);
        }
        float t0 = tanhf(a0), t1 = tanhf(a1);
        float ss = t0 * t0 + t1 * t1;
        ss += __shfl_xor_sync(0xffffffffu, ss, 16);
        ss += __shfl_xor_sync(0xffffffffu, ss, 8);
        ss += __shfl_xor_sync(0xffffffffu, ss, 4);
        ss += __shfl_xor_sync(0xffffffffu, ss, 2);
        ss += __shfl_xor_sync(0xffffffffu, ss, 1);
        float sc = __fdividef(1.f, fmaxf(sqrtf(ss), 1e-12f));
        *reinterpret_cast<float2*>(g_x + (size_t)(NI + u) * 64 + 2 * lane) =
            make_float2(t0 * sc, t1 * sc);
    }
}

// ---------------- preprocessing (R9 separate kernels — fastest known) -------------
__global__ void k_hist(const int* __restrict__ src, const int* __restrict__ dst, int E) {
    int i = blockIdx.x * blockDim.x + threadIdx.x;
    if (i < E) {
        atomicAdd(&g_cnt[dst[i]], 1);
        atomicAdd(&g_deg[src[i]], 1);
    }
}

__global__ void k_scan1() {
    __shared__ int sd[1024];
    int t = threadIdx.x;
    int idx = blockIdx.x * 1024 + t;
    int v = (idx < NN) ? g_cnt[idx] : 0;
    sd[t] = v;
    __syncthreads();
    for (int off = 1; off < 1024; off <<= 1) {
        int add = (t >= off) ? sd[t - off] : 0;
        __syncthreads();
        sd[t] += add;
        __syncthreads();
    }
    if (idx < NN) g_start[idx + 1] = sd[t];
    if (t == 0) g_bsum[blockIdx.x] = sd[1023];
}

__global__ void k_scan23(int nb) {
    __shared__ int s[128];
    int t = threadIdx.x;
    if (t < 128) s[t] = (t < nb) ? g_bsum[t] : 0;
    __syncthreads();
    for (int off = 1; off < 128; off <<= 1) {
        int add = (t >= off && t < 128) ? s[t - off] : 0;
        __syncthreads();
        if (t < 128) s[t] += add;
        __syncthreads();
    }
    int boff = (blockIdx.x == 0) ? 0 : s[blockIdx.x - 1];
    int idx = blockIdx.x * 1024 + t;
    if (idx < NN) {
        int v = g_start[idx + 1] + boff;
        g_start[idx + 1] = v;
        if (idx + 1 < NN) g_cursor[idx + 1] = v;
        int d = g_deg[idx];
        g_dinv[idx] = (d > 0) ? rsqrtf((float)d) : 0.f;
    }
    if (idx == 0) { g_start[0] = 0; g_cursor[0] = 0; }
}

__global__ void k_scatter(const int* __restrict__ src, const int* __restrict__ dst, int E) {
    int i = blockIdx.x * blockDim.x + threadIdx.x;
    if (i < E) {
        int d = dst[i];
        int p = atomicAdd(&g_cursor[d], 1);
        g_csr[p] = src[i];
    }
}

// ======================= GEMM core (R9: 8 rows x 8 cols / thread, 128 thr) ==========
struct Acc8x4 { unsigned long long a[8][4]; };

__device__ __forceinline__ void gemm_pass(const float* __restrict__ xs,
                                          const float* __restrict__ ws,
                                          int rg, int c0, int swz, Acc8x4& A) {
#pragma unroll
    for (int rr = 0; rr < 8; rr++)
#pragma unroll
        for (int p = 0; p < 4; p++) A.a[rr][p] = 0ull;
#pragma unroll 4
    for (int kb = 0; kb < 64; kb += 4) {
        float4 a4[8];
#pragma unroll
        for (int rr = 0; rr < 8; rr++)
            a4[rr] = *(const float4*)&xs[(rg * 8 + rr) * 64 + (kb ^ swz)];
#pragma unroll
        for (int j = 0; j < 4; j++) {
            int k = kb + j;
            ulonglong2 wA = *(const ulonglong2*)&ws[k * 64 + c0];
            ulonglong2 wB = *(const ulonglong2*)&ws[k * 64 + c0 + 4];
#pragma unroll
            for (int rr = 0; rr < 8; rr++) {
                float a = (j == 0) ? a4[rr].x : (j == 1) ? a4[rr].y
                          : (j == 2) ? a4[rr].z : a4[rr].w;
                unsigned long long aa = packdup(a);
                ffma2(A.a[rr][0], aa, wA.x); ffma2(A.a[rr][1], aa, wA.y);
                ffma2(A.a[rr][2], aa, wB.x); ffma2(A.a[rr][3], aa, wB.y);
            }
        }
    }
}

__device__ __forceinline__ void load_xs(float* __restrict__ xs,
                                        const float* __restrict__ in,
                                        int row0, int n, int tid) {
    for (int i = tid * 4; i < 8192; i += 512) {
        int r = i >> 6, k = i & 63;
        int sw = ((r >> 3) & 7) * 8;
        int gr = row0 + r;
        float4 v = (gr < n) ? *(const float4*)(in + (size_t)gr * 64 + k)
                            : make_float4(0.f, 0.f, 0.f, 0.f);
        *(float4*)&xs[r * 64 + (k ^ sw)] = v;
    }
}

// ---------------- fused dual GEMM, two passes, reloaded weight buffer ----------
__global__ void __launch_bounds__(128, 4) k_dual(const float* __restrict__ in,
                                                 const float* __restrict__ Wg,
                                                 const float* __restrict__ Wl,
                                                 const float* __restrict__ bias,
                                                 const float* __restrict__ idw,
                                                 float* __restrict__ xw,
                                                 float* __restrict__ xhat, int n) {
    __shared__ __align__(16) float ws[4096];
    __shared__ __align__(16) float xs[8192];
    int tid = threadIdx.x;
    int rg = tid >> 3;
    int cg = tid & 7;
    int c0 = cg * 8;
    int swz = (rg & 7) * 8;
    int row0 = blockIdx.x * 128;

    for (int i = tid; i < 4096; i += 128) ws[i] = Wg[i];
    load_xs(xs, in, row0, n, tid);
    __syncthreads();

    Acc8x4 A;
    gemm_pass(xs, ws, rg, c0, swz, A);
#pragma unroll
    for (int rr = 0; rr < 8; rr++) {
        int r = row0 + rg * 8 + rr;
        if (r < n) {
            size_t base = (size_t)r * 64 + c0;
            float2 v0 = unpack2(A.a[rr][0]), v1 = unpack2(A.a[rr][1]);
            float2 v2 = unpack2(A.a[rr][2]), v3 = unpack2(A.a[rr][3]);
            *(float4*)(xw + base) = make_float4(v0.x, v0.y, v1.x, v1.y);
            *(float4*)(xw + base + 4) = make_float4(v2.x, v2.y, v3.x, v3.y);
        }
    }
    __syncthreads();

    for (int i = tid; i < 4096; i += 128) {
        int k = i >> 6, c = i & 63;
        ws[i] = Wl[c * 64 + k];
    }
    __syncthreads();

    gemm_pass(xs, ws, rg, c0, swz, A);
    float4 b0 = *(const float4*)(bias + c0);
    float4 b1 = *(const float4*)(bias + c0 + 4);
#pragma unroll
    for (int rr = 0; rr < 8; rr++) {
        int r = row0 + rg * 8 + rr;
        if (r < n) {
            size_t base = (size_t)r * 64 + c0;
            float2 u0 = unpack2(A.a[rr][0]), u1 = unpack2(A.a[rr][1]);
            float2 u2 = unpack2(A.a[rr][2]), u3 = unpack2(A.a[rr][3]);
            float4 i0 = *(const float4*)(idw + base);
            float4 i1 = *(const float4*)(idw + base + 4);
            *(float4*)(xhat + base) = make_float4(
                leaky(u0.x + b0.x) + i0.x, leaky(u0.y + b0.y) + i0.y,
                leaky(u1.x + b0.z) + i0.z, leaky(u1.y + b0.w) + i0.w);
            *(float4*)(xhat + base + 4) = make_float4(
                leaky(u2.x + b1.x) + i1.x, leaky(u2.y + b1.y) + i1.y,
                leaky(u3.x + b1.z) + i1.z, leaky(u3.y + b1.w) + i1.w);
        }
    }
}

// ---------------- final GEMM: v = leaky(h@W' + b + xhat); write outb & out2 --------
__global__ void __launch_bounds__(128, 4) k_final(const float* __restrict__ in,
                                                  const float* __restrict__ W,
                                                  const float* __restrict__ bias,
                                                  const float* __restrict__ add,
                                                  float* __restrict__ outb,
                                                  float* __restrict__ out2, int n) {
    __shared__ __align__(16) float ws[4096];
    __shared__ __align__(16) float xs[8192];
    int tid = threadIdx.x;
    int rg = tid >> 3, cg = tid & 7;
    int c0 = cg * 8;
    int swz = (rg & 7) * 8;
    int row0 = blockIdx.x * 128;

    for (int i = tid; i < 4096; i += 128) {
        int k = i >> 6, c = i & 63;
        ws[i] = W[c * 64 + k];
    }
    load_xs(xs, in, row0, n, tid);
    __syncthreads();

    Acc8x4 A;
    gemm_pass(xs, ws, rg, c0, swz, A);
    float4 b0 = *(const float4*)(bias + c0);
    float4 b1 = *(const float4*)(bias + c0 + 4);
#pragma unroll
    for (int rr = 0; rr < 8; rr++) {
        int r = row0 + rg * 8 + rr;
        if (r < n) {
            size_t base = (size_t)r * 64 + c0;
            float2 u0 = unpack2(A.a[rr][0]), u1 = unpack2(A.a[rr][1]);
            float2 u2 = unpack2(A.a[rr][2]), u3 = unpack2(A.a[rr][3]);
            float4 h0 = *(const float4*)(add + base);
            float4 h1 = *(const float4*)(add + base + 4);
            float4 o0 = make_float4(leaky(u0.x + b0.x + h0.x), leaky(u0.y + b0.y + h0.y),
                                    leaky(u1.x + b0.z + h0.z), leaky(u1.y + b0.w + h0.w));
            float4 o1 = make_float4(leaky(u2.x + b1.x + h1.x), leaky(u2.y + b1.y + h1.y),
                                    leaky(u3.x + b1.z + h1.z), leaky(u3.y + b1.w + h1.w));
            *(float4*)(outb + base) = o0;
            *(float4*)(outb + base + 4) = o1;
            *(float4*)(out2 + (size_t)r * 128 + c0) = o0;
            *(float4*)(out2 + (size_t)r * 128 + c0 + 4) = o1;
        }
    }
}

// ---------------- GAT aggregation: 2 nodes/warp (16 lanes each), no-max softmax ----
// Halved SHFL depth (xor 8/4/2/1 within halves), scalar softmax math shared
// across both halves, 2 edge-pairs unrolled for ILP.
__global__ void __launch_bounds__(256) k_agg() {
    int gw = (blockIdx.x * blockDim.x + threadIdx.x) >> 5;
    int lane = threadIdx.x & 31;
    int half = lane >> 4;
    int hl = lane & 15;
    int w = gw * 2 + half;
    bool valid = (w < NN);
    int s = 0, cnt = 0;
    if (valid) { s = g_start[w]; cnt = g_start[w + 1] - s; }
    float4 xv = make_float4(0.f, 0.f, 0.f, 0.f);
    if (valid) xv = *(const float4*)(g_xw + (size_t)w * 64 + hl * 4);
    int cntmax = max(cnt, __shfl_xor_sync(0xffffffffu, cnt, 16));
    const float NEGINF = __int_as_float(0xff800000);
    float z = 0.f;
    float4 acc = make_float4(0.f, 0.f, 0.f, 0.f);
    int u_l = 0; float dv_l = 0.f;
    if (hl < cnt) { u_l = g_csr[s + hl]; dv_l = g_dinv[u_l]; }
    int hbase = half << 4;
    for (int i = 0; i < cntmax; i += 2) {
        int j = i & 15;
        if (j == 0 && i > 0) {
            int idx = i + hl;
            u_l = (idx < cnt) ? g_csr[s + idx] : 0;
            dv_l = (idx < cnt) ? g_dinv[u_l] : 0.f;
        }
        int u0 = __shfl_sync(0xffffffffu, u_l, hbase + j);
        int u1 = __shfl_sync(0xffffffffu, u_l, hbase + j + 1);
        float dv0 = __shfl_sync(0xffffffffu, dv_l, hbase + j);
        float dv1 = __shfl_sync(0xffffffffu, dv_l, hbase + j + 1);
        float4 a0 = *(const float4*)(g_xw + (size_t)u0 * 64 + hl * 4);
        float4 a1 = *(const float4*)(g_xw + (size_t)u1 * 64 + hl * 4);
        float p0 = fmaf(xv.x, a0.x, fmaf(xv.y, a0.y, fmaf(xv.z, a0.z, xv.w * a0.w)));
        float p1 = fmaf(xv.x, a1.x, fmaf(xv.y, a1.y, fmaf(xv.z, a1.z, xv.w * a1.w)));
#pragma unroll
        for (int o = 8; o; o >>= 1) {
            p0 += __shfl_xor_sync(0xffffffffu, p0, o);
            p1 += __shfl_xor_sync(0xffffffffu, p1, o);
        }
        float lg0 = (i < cnt) ? p0 * __fdividef(1.f, 1.f + __expf(-p0 * dv0)) : NEGINF;
        float lg1 = (i + 1 < cnt) ? p1 * __fdividef(1.f, 1.f + __expf(-p1 * dv1)) : NEGINF;
        float pe0 = __expf(lg0);   // 0 for masked edges (no-max: logits small)
        float pe1 = __expf(lg1);
        z += pe0 + pe1;
        acc.x += fmaf(pe0, a0.x, pe1 * a1.x);
        acc.y += fmaf(pe0, a0.y, pe1 * a1.y);
        acc.z += fmaf(pe0, a0.z, pe1 * a1.z);
        acc.w += fmaf(pe0, a0.w, pe1 * a1.w);
    }
    if (valid) {
        float inv = __fdividef(1.f, z + 1e-16f);
        *(float4*)(g_h + (size_t)w * 64 + hl * 4) =
            make_float4(leaky(acc.x * inv), leaky(acc.y * inv),
                        leaky(acc.z * inv), leaky(acc.w * inv));
    }
}

// ---------------- launch ----------------
extern "C" void kernel_launch(void* const* d_in, const int* in_sizes, int n_in,
                              void* d_out, int out_size) {
    const float* features = (const float*)d_in[0];
    const float* user_features = (const float*)d_in[1];
    const float* id_emb = (const float*)d_in[2];
    const float* user_mlp_w = (const float*)d_in[3];
    const float* user_mlp_b = (const float*)d_in[4];
    const float* gat1_w = (const float*)d_in[5];
    const float* lin1_w = (const float*)d_in[6];
    const float* lin1_b = (const float*)d_in[7];
    const float* g1_w = (const float*)d_in[8];
    const float* g1_b = (const float*)d_in[9];
    const float* gat2_w = (const float*)d_in[10];
    const float* lin2_w = (const float*)d_in[11];
    const float* lin2_b = (const float*)d_in[12];
    const float* g2_w = (const float*)d_in[13];
    const float* g2_b = (const float*)d_in[14];
    const int* edge_index = (const int*)d_in[15];
    float* out = (float*)d_out;

    int E = in_sizes[15] / 2;
    if (E > EE) E = EE;
    const int* src = edge_index;
    const int* dst = edge_index + E;

    float *p_x, *p_xw, *p_h, *p_xhat, *p_xcur;
    cudaGetSymbolAddress((void**)&p_x, g_x);
    cudaGetSymbolAddress((void**)&p_xw, g_xw);
    cudaGetSymbolAddress((void**)&p_h, g_h);
    cudaGetSymbolAddress((void**)&p_xhat, g_xhat);
    cudaGetSymbolAddress((void**)&p_xcur, g_xcur);

    int ge = (E + 255) / 256;
    int nb = (NN + 1023) / 1024;
    const int GT = (NN + 127) / 128;      // 782 gemm tiles
    const int AGB = (NN / 2 + 7) / 8;     // agg: 2 nodes/warp, 8 warps/block

    // 1: build x (items+users) + zero counters
    k_build<<<ITEM_B + USER_B, 256>>>(features, user_features, user_mlp_w, user_mlp_b);
    // 2: degree histograms
    k_hist<<<ge, 256>>>(src, dst, E);
    // 3: per-block scan
    k_scan1<<<nb, 1024>>>();
    // 4: hop-1 dual GEMM  (profiled slot)
    k_dual<<<GT, 128>>>(p_x, gat1_w, lin1_w, lin1_b, id_emb, p_xw, p_xhat, NN);
    // 5: scan finalize + prep
    k_scan23<<<nb, 1024>>>(nb);
    // 6: CSR scatter
    k_scatter<<<ge, 256>>>(src, dst, E);
    // 7-8: hop-1 agg + final
    k_agg<<<AGB, 256>>>();
    k_final<<<GT, 128>>>(p_h, g1_w, g1_b, p_xhat, p_xcur, out, NN);
    // 9-11: hop 2
    k_dual<<<GT, 128>>>(p_xcur, gat2_w, lin2_w, lin2_b, id_emb, p_xw, p_xhat, NN);
    k_agg<<<AGB, 256>>>();
    k_final<<<GT, 128>>>(p_h, g2_w, g2_b, p_xhat, p_x, out + 64, NN);
}

// round 14
// speedup vs baseline: 1.1313x; 1.0628x over previous
#include <cuda_runtime.h>
#include <math.h>

#define NI 80000
#define NU 20000
#define NN 100000
#define EE 1000000

// ---------------- scratch (static device globals; no allocs) ----------------
__device__ float g_x[NN * 64];
__device__ float g_xw[NN * 64];
__device__ float g_h[NN * 64];
__device__ float g_xhat[NN * 64];
__device__ float g_xcur[NN * 64];
__device__ int   g_cnt[NN];
__device__ int   g_deg[NN];
__device__ int   g_start[NN + 1];
__device__ int   g_cursor[NN];
__device__ int   g_csr[EE];
__device__ float g_dinv[NN];
__device__ int   g_bsum[128];

__device__ __forceinline__ float leaky(float v) { return v >= 0.f ? v : 0.01f * v; }

__device__ __forceinline__ unsigned long long packdup(float a) {
    unsigned long long r;
    asm("mov.b64 %0, {%1, %1};" : "=l"(r) : "f"(a));
    return r;
}
__device__ __forceinline__ void ffma2(unsigned long long& d, unsigned long long a,
                                      unsigned long long b) {
    asm("fma.rn.f32x2 %0, %1, %2, %0;" : "+l"(d) : "l"(a), "l"(b));
}
__device__ __forceinline__ float2 unpack2(unsigned long long v) {
    float2 f;
    asm("mov.b64 {%0, %1}, %2;" : "=f"(f.x), "=f"(f.y) : "l"(v));
    return f;
}

// ---------------- zero counters (side stream, hidden) ----------------
__global__ void k_zero() {
    int i = blockIdx.x * blockDim.x + threadIdx.x;
    if (i < NN) { g_cnt[i] = 0; g_deg[i] = 0; }
}

// ---------------- build x (items + users), one launch ----------
#define ITEM_B (NI / 8)
#define USER_B 592
__global__ void __launch_bounds__(256) k_build(const float* __restrict__ f,
                                               const float* __restrict__ uf,
                                               const float* __restrict__ Wu,
                                               const float* __restrict__ bu) {
    __shared__ __align__(16) float ws[128 * 64];
    int tid = threadIdx.x;

    if (blockIdx.x < ITEM_B) {
        int w = blockIdx.x * 8 + (tid >> 5);
        int lane = tid & 31;
        float2 v = *reinterpret_cast<const float2*>(f + (size_t)w * 64 + 2 * lane);
        float ss = v.x * v.x + v.y * v.y;
        ss += __shfl_xor_sync(0xffffffffu, ss, 16);
        ss += __shfl_xor_sync(0xffffffffu, ss, 8);
        ss += __shfl_xor_sync(0xffffffffu, ss, 4);
        ss += __shfl_xor_sync(0xffffffffu, ss, 2);
        ss += __shfl_xor_sync(0xffffffffu, ss, 1);
        float sc = __fdividef(1.f, fmaxf(sqrtf(ss), 1e-12f));
        *reinterpret_cast<float2*>(g_x + (size_t)w * 64 + 2 * lane) =
            make_float2(v.x * sc, v.y * sc);
        return;
    }
    int ub = blockIdx.x - ITEM_B;
    for (int i = tid; i < 8192; i += 256) {
        int c = i >> 7, k = i & 127;
        ws[k * 64 + c] = Wu[i];
    }
    __syncthreads();
    int lane = tid & 31, wp = tid >> 5;
    for (int u = ub * 8 + wp; u < NU; u += USER_B * 8) {
        float4 my = *reinterpret_cast<const float4*>(uf + (size_t)u * 128 + lane * 4);
        float a0 = bu[2 * lane], a1 = bu[2 * lane + 1];
        for (int sl = 0; sl < 32; sl++) {
            float v0 = __shfl_sync(0xffffffffu, my.x, sl);
            float v1 = __shfl_sync(0xffffffffu, my.y, sl);
            float v2 = __shfl_sync(0xffffffffu, my.z, sl);
            float v3 = __shfl_sync(0xffffffffu, my.w, sl);
            int k0 = sl * 4;
            float2 w;
            w = *reinterpret_cast<const float2*>(&ws[(k0 + 0) * 64 + 2 * lane]);
            a0 = fmaf(v0, w.x, a0); a1 = fmaf(v0, w.y, a1);
            w = *reinterpret_cast<const float2*>(&ws[(k0 + 1) * 64 + 2 * lane]);
            a0 = fmaf(v1, w.x, a0); a1 = fmaf(v1, w.y, a1);
            w = *reinterpret_cast<const float2*>(&ws[(k0 + 2) * 64 + 2 * lane]);
            a0 = fmaf(v2, w.x, a0); a1 = fmaf(v2, w.y, a1);
            w = *reinterpret_cast<const float2*>(&ws[(k0 + 3) * 64 + 2 * lane]);
            a0 = fmaf(v3, w.x, a0); a1 = fmaf(v3, w.y, a1);
        }
        float t0 = tanhf(a0), t1 = tanhf(a1);
        float ss = t0 * t0 + t1 * t1;
        ss += __shfl_xor_sync(0xffffffffu, ss, 16);
        ss += __shfl_xor_sync(0xffffffffu, ss, 8);
        ss += __shfl_xor_sync(0xffffffffu, ss, 4);
        ss += __shfl_xor_sync(0xffffffffu, ss, 2);
        ss += __shfl_xor_sync(0xffffffffu, ss, 1);
        float sc = __fdividef(1.f, fmaxf(sqrtf(ss), 1e-12f));
        *reinterpret_cast<float2*>(g_x + (size_t)(NI + u) * 64 + 2 * lane) =
            make_float2(t0 * sc, t1 * sc);
    }
}

// ---------------- preprocessing ----------------
__global__ void k_hist(const int* __restrict__ src, const int* __restrict__ dst, int E) {
    int i = blockIdx.x * blockDim.x + threadIdx.x;
    if (i < E) {
        atomicAdd(&g_cnt[dst[i]], 1);
        atomicAdd(&g_deg[src[i]], 1);
    }
}

__global__ void k_scan1() {
    __shared__ int sd[1024];
    int t = threadIdx.x;
    int idx = blockIdx.x * 1024 + t;
    int v = (idx < NN) ? g_cnt[idx] : 0;
    sd[t] = v;
    __syncthreads();
    for (int off = 1; off < 1024; off <<= 1) {
        int add = (t >= off) ? sd[t - off] : 0;
        __syncthreads();
        sd[t] += add;
        __syncthreads();
    }
    if (idx < NN) g_start[idx + 1] = sd[t];
    if (t == 0) g_bsum[blockIdx.x] = sd[1023];
}

__global__ void k_scan23(int nb) {
    __shared__ int s[128];
    int t = threadIdx.x;
    if (t < 128) s[t] = (t < nb) ? g_bsum[t] : 0;
    __syncthreads();
    for (int off = 1; off < 128; off <<= 1) {
        int add = (t >= off && t < 128) ? s[t - off] : 0;
        __syncthreads();
        if (t < 128) s[t] += add;
        __syncthreads();
    }
    int boff = (blockIdx.x == 0) ? 0 : s[blockIdx.x - 1];
    int idx = blockIdx.x * 1024 + t;
    if (idx < NN) {
        int v = g_start[idx + 1] + boff;
        g_start[idx + 1] = v;
        if (idx + 1 < NN) g_cursor[idx + 1] = v;
        int d = g_deg[idx];
        g_dinv[idx] = (d > 0) ? rsqrtf((float)d) : 0.f;
    }
    if (idx == 0) { g_start[0] = 0; g_cursor[0] = 0; }
}

__global__ void k_scatter(const int* __restrict__ src, const int* __restrict__ dst, int E) {
    int i = blockIdx.x * blockDim.x + threadIdx.x;
    if (i < E) {
        int d = dst[i];
        int p = atomicAdd(&g_cursor[d], 1);
        g_csr[p] = src[i];
    }
}

// ======================= GEMM core (8 rows x 8 cols / thread, 128 thr) ==========
struct Acc8x4 { unsigned long long a[8][4]; };

__device__ __forceinline__ void gemm_pass(const float* __restrict__ xs,
                                          const float* __restrict__ ws,
                                          int rg, int c0, int swz, Acc8x4& A) {
#pragma unroll
    for (int rr = 0; rr < 8; rr++)
#pragma unroll
        for (int p = 0; p < 4; p++) A.a[rr][p] = 0ull;
#pragma unroll 4
    for (int kb = 0; kb < 64; kb += 4) {
        float4 a4[8];
#pragma unroll
        for (int rr = 0; rr < 8; rr++)
            a4[rr] = *(const float4*)&xs[(rg * 8 + rr) * 64 + (kb ^ swz)];
#pragma unroll
        for (int j = 0; j < 4; j++) {
            int k = kb + j;
            ulonglong2 wA = *(const ulonglong2*)&ws[k * 64 + c0];
            ulonglong2 wB = *(const ulonglong2*)&ws[k * 64 + c0 + 4];
#pragma unroll
            for (int rr = 0; rr < 8; rr++) {
                float a = (j == 0) ? a4[rr].x : (j == 1) ? a4[rr].y
                          : (j == 2) ? a4[rr].z : a4[rr].w;
                unsigned long long aa = packdup(a);
                ffma2(A.a[rr][0], aa, wA.x); ffma2(A.a[rr][1], aa, wA.y);
                ffma2(A.a[rr][2], aa, wB.x); ffma2(A.a[rr][3], aa, wB.y);
            }
        }
    }
}

__device__ __forceinline__ void load_xs(float* __restrict__ xs,
                                        const float* __restrict__ in,
                                        int row0, int n, int tid) {
    for (int i = tid * 4; i < 8192; i += 512) {
        int r = i >> 6, k = i & 63;
        int sw = ((r >> 3) & 7) * 8;
        int gr = row0 + r;
        float4 v = (gr < n) ? *(const float4*)(in + (size_t)gr * 64 + k)
                            : make_float4(0.f, 0.f, 0.f, 0.f);
        *(float4*)&xs[r * 64 + (k ^ sw)] = v;
    }
}

// ---------------- fused dual GEMM, two passes, reloaded weight buffer ----------
__global__ void __launch_bounds__(128, 4) k_dual(const float* __restrict__ in,
                                                 const float* __restrict__ Wg,
                                                 const float* __restrict__ Wl,
                                                 const float* __restrict__ bias,
                                                 const float* __restrict__ idw,
                                                 float* __restrict__ xw,
                                                 float* __restrict__ xhat, int n) {
    __shared__ __align__(16) float ws[4096];
    __shared__ __align__(16) float xs[8192];
    int tid = threadIdx.x;
    int rg = tid >> 3;
    int cg = tid & 7;
    int c0 = cg * 8;
    int swz = (rg & 7) * 8;
    int row0 = blockIdx.x * 128;

    for (int i = tid; i < 4096; i += 128) ws[i] = Wg[i];
    load_xs(xs, in, row0, n, tid);
    __syncthreads();

    Acc8x4 A;
    gemm_pass(xs, ws, rg, c0, swz, A);
#pragma unroll
    for (int rr = 0; rr < 8; rr++) {
        int r = row0 + rg * 8 + rr;
        if (r < n) {
            size_t base = (size_t)r * 64 + c0;
            float2 v0 = unpack2(A.a[rr][0]), v1 = unpack2(A.a[rr][1]);
            float2 v2 = unpack2(A.a[rr][2]), v3 = unpack2(A.a[rr][3]);
            *(float4*)(xw + base) = make_float4(v0.x, v0.y, v1.x, v1.y);
            *(float4*)(xw + base + 4) = make_float4(v2.x, v2.y, v3.x, v3.y);
        }
    }
    __syncthreads();

    for (int i = tid; i < 4096; i += 128) {
        int k = i >> 6, c = i & 63;
        ws[i] = Wl[c * 64 + k];
    }
    __syncthreads();

    gemm_pass(xs, ws, rg, c0, swz, A);
    float4 b0 = *(const float4*)(bias + c0);
    float4 b1 = *(const float4*)(bias + c0 + 4);
#pragma unroll
    for (int rr = 0; rr < 8; rr++) {
        int r = row0 + rg * 8 + rr;
        if (r < n) {
            size_t base = (size_t)r * 64 + c0;
            float2 u0 = unpack2(A.a[rr][0]), u1 = unpack2(A.a[rr][1]);
            float2 u2 = unpack2(A.a[rr][2]), u3 = unpack2(A.a[rr][3]);
            float4 i0 = *(const float4*)(idw + base);
            float4 i1 = *(const float4*)(idw + base + 4);
            *(float4*)(xhat + base) = make_float4(
                leaky(u0.x + b0.x) + i0.x, leaky(u0.y + b0.y) + i0.y,
                leaky(u1.x + b0.z) + i0.z, leaky(u1.y + b0.w) + i0.w);
            *(float4*)(xhat + base + 4) = make_float4(
                leaky(u2.x + b1.x) + i1.x, leaky(u2.y + b1.y) + i1.y,
                leaky(u3.x + b1.z) + i1.z, leaky(u3.y + b1.w) + i1.w);
        }
    }
}

// ---------------- final GEMM: v = leaky(h@W' + b + xhat); out2 always, outb opt ----
__global__ void __launch_bounds__(128, 4) k_final(const float* __restrict__ in,
                                                  const float* __restrict__ W,
                                                  const float* __restrict__ bias,
                                                  const float* __restrict__ add,
                                                  float* __restrict__ outb,
                                                  float* __restrict__ out2,
                                                  int write_outb, int n) {
    __shared__ __align__(16) float ws[4096];
    __shared__ __align__(16) float xs[8192];
    int tid = threadIdx.x;
    int rg = tid >> 3, cg = tid & 7;
    int c0 = cg * 8;
    int swz = (rg & 7) * 8;
    int row0 = blockIdx.x * 128;

    for (int i = tid; i < 4096; i += 128) {
        int k = i >> 6, c = i & 63;
        ws[i] = W[c * 64 + k];
    }
    load_xs(xs, in, row0, n, tid);
    __syncthreads();

    Acc8x4 A;
    gemm_pass(xs, ws, rg, c0, swz, A);
    float4 b0 = *(const float4*)(bias + c0);
    float4 b1 = *(const float4*)(bias + c0 + 4);
#pragma unroll
    for (int rr = 0; rr < 8; rr++) {
        int r = row0 + rg * 8 + rr;
        if (r < n) {
            size_t base = (size_t)r * 64 + c0;
            float2 u0 = unpack2(A.a[rr][0]), u1 = unpack2(A.a[rr][1]);
            float2 u2 = unpack2(A.a[rr][2]), u3 = unpack2(A.a[rr][3]);
            float4 h0 = *(const float4*)(add + base);
            float4 h1 = *(const float4*)(add + base + 4);
            float4 o0 = make_float4(leaky(u0.x + b0.x + h0.x), leaky(u0.y + b0.y + h0.y),
                                    leaky(u1.x + b0.z + h0.z), leaky(u1.y + b0.w + h0.w));
            float4 o1 = make_float4(leaky(u2.x + b1.x + h1.x), leaky(u2.y + b1.y + h1.y),
                                    leaky(u3.x + b1.z + h1.z), leaky(u3.y + b1.w + h1.w));
            if (write_outb) {
                *(float4*)(outb + base) = o0;
                *(float4*)(outb + base + 4) = o1;
            }
            *(float4*)(out2 + (size_t)r * 128 + c0) = o0;
            *(float4*)(out2 + (size_t)r * 128 + c0 + 4) = o1;
        }
    }
}

// ---------------- GAT aggregation: 2 nodes/warp (16 lanes each), no-max softmax ----
__global__ void __launch_bounds__(256) k_agg() {
    int gw = (blockIdx.x * blockDim.x + threadIdx.x) >> 5;
    int lane = threadIdx.x & 31;
    int half = lane >> 4;
    int hl = lane & 15;
    int w = gw * 2 + half;
    bool valid = (w < NN);
    int s = 0, cnt = 0;
    if (valid) { s = g_start[w]; cnt = g_start[w + 1] - s; }
    float4 xv = make_float4(0.f, 0.f, 0.f, 0.f);
    if (valid) xv = *(const float4*)(g_xw + (size_t)w * 64 + hl * 4);
    int cntmax = max(cnt, __shfl_xor_sync(0xffffffffu, cnt, 16));
    const float NEGINF = __int_as_float(0xff800000);
    float z = 0.f;
    float4 acc = make_float4(0.f, 0.f, 0.f, 0.f);
    int u_l = 0; float dv_l = 0.f;
    if (hl < cnt) { u_l = g_csr[s + hl]; dv_l = g_dinv[u_l]; }
    int hbase = half << 4;
    for (int i = 0; i < cntmax; i += 2) {
        int j = i & 15;
        if (j == 0 && i > 0) {
            int idx = i + hl;
            u_l = (idx < cnt) ? g_csr[s + idx] : 0;
            dv_l = (idx < cnt) ? g_dinv[u_l] : 0.f;
        }
        int u0 = __shfl_sync(0xffffffffu, u_l, hbase + j);
        int u1 = __shfl_sync(0xffffffffu, u_l, hbase + j + 1);
        float dv0 = __shfl_sync(0xffffffffu, dv_l, hbase + j);
        float dv1 = __shfl_sync(0xffffffffu, dv_l, hbase + j + 1);
        float4 a0 = *(const float4*)(g_xw + (size_t)u0 * 64 + hl * 4);
        float4 a1 = *(const float4*)(g_xw + (size_t)u1 * 64 + hl * 4);
        float p0 = fmaf(xv.x, a0.x, fmaf(xv.y, a0.y, fmaf(xv.z, a0.z, xv.w * a0.w)));
        float p1 = fmaf(xv.x, a1.x, fmaf(xv.y, a1.y, fmaf(xv.z, a1.z, xv.w * a1.w)));
#pragma unroll
        for (int o = 8; o; o >>= 1) {
            p0 += __shfl_xor_sync(0xffffffffu, p0, o);
            p1 += __shfl_xor_sync(0xffffffffu, p1, o);
        }
        float lg0 = (i < cnt) ? p0 * __fdividef(1.f, 1.f + __expf(-p0 * dv0)) : NEGINF;
        float lg1 = (i + 1 < cnt) ? p1 * __fdividef(1.f, 1.f + __expf(-p1 * dv1)) : NEGINF;
        float pe0 = __expf(lg0);
        float pe1 = __expf(lg1);
        z += pe0 + pe1;
        acc.x += fmaf(pe0, a0.x, pe1 * a1.x);
        acc.y += fmaf(pe0, a0.y, pe1 * a1.y);
        acc.z += fmaf(pe0, a0.z, pe1 * a1.z);
        acc.w += fmaf(pe0, a0.w, pe1 * a1.w);
    }
    if (valid) {
        float inv = __fdividef(1.f, z + 1e-16f);
        *(float4*)(g_h + (size_t)w * 64 + hl * 4) =
            make_float4(leaky(acc.x * inv), leaky(acc.y * inv),
                        leaky(acc.z * inv), leaky(acc.w * inv));
    }
}

// ---------------- launch ----------------
extern "C" void kernel_launch(void* const* d_in, const int* in_sizes, int n_in,
                              void* d_out, int out_size) {
    const float* features = (const float*)d_in[0];
    const float* user_features = (const float*)d_in[1];
    const float* id_emb = (const float*)d_in[2];
    const float* user_mlp_w = (const float*)d_in[3];
    const float* user_mlp_b = (const float*)d_in[4];
    const float* gat1_w = (const float*)d_in[5];
    const float* lin1_w = (const float*)d_in[6];
    const float* lin1_b = (const float*)d_in[7];
    const float* g1_w = (const float*)d_in[8];
    const float* g1_b = (const float*)d_in[9];
    const float* gat2_w = (const float*)d_in[10];
    const float* lin2_w = (const float*)d_in[11];
    const float* lin2_b = (const float*)d_in[12];
    const float* g2_w = (const float*)d_in[13];
    const float* g2_b = (const float*)d_in[14];
    const int* edge_index = (const int*)d_in[15];
    float* out = (float*)d_out;

    int E = in_sizes[15] / 2;
    if (E > EE) E = EE;
    const int* src = edge_index;
    const int* dst = edge_index + E;

    float *p_x, *p_xw, *p_h, *p_xhat, *p_xcur;
    cudaGetSymbolAddress((void**)&p_x, g_x);
    cudaGetSymbolAddress((void**)&p_xw, g_xw);
    cudaGetSymbolAddress((void**)&p_h, g_h);
    cudaGetSymbolAddress((void**)&p_xhat, g_xhat);
    cudaGetSymbolAddress((void**)&p_xcur, g_xcur);

    int gn = (NN + 255) / 256;
    int ge = (E + 255) / 256;
    int nb = (NN + 1023) / 1024;
    const int GT = (NN + 127) / 128;      // 782 gemm tiles
    const int AGB = (NN / 2 + 7) / 8;     // agg: 2 nodes/warp, 8 warps/block

    // side stream + fork/join events (host-side objects, created once)
    static cudaStream_t sB = nullptr;
    static cudaEvent_t eFork = nullptr, eJoin = nullptr;
    if (sB == nullptr) {
        cudaStreamCreateWithFlags(&sB, cudaStreamNonBlocking);
        cudaEventCreateWithFlags(&eFork, cudaEventDisableTiming);
        cudaEventCreateWithFlags(&eJoin, cudaEventDisableTiming);
    }

    // fork: side stream joins the capture DAG
    cudaEventRecord(eFork, 0);
    cudaStreamWaitEvent(sB, eFork, 0);

    // ---- parallel DAG ----
    // sB: zero -> hist -> scan1 -> scan23 -> scatter   (CSR chain; needs only edges)
    // s0: build -> dual1                                (feature chain)
    k_zero<<<gn, 256, 0, sB>>>();                                        // 1
    k_build<<<ITEM_B + USER_B, 256>>>(features, user_features,           // 2
                                      user_mlp_w, user_mlp_b);
    k_hist<<<ge, 256, 0, sB>>>(src, dst, E);                             // 3
    k_dual<<<GT, 128>>>(p_x, gat1_w, lin1_w, lin1_b, id_emb,             // 4 (profiled)
                        p_xw, p_xhat, NN);
    k_scan1<<<nb, 1024, 0, sB>>>();                                      // 5
    k_scan23<<<nb, 1024, 0, sB>>>(nb);                                   // 6
    k_scatter<<<ge, 256, 0, sB>>>(src, dst, E);                          // 7

    // join: agg needs csr/start/dinv (sB) + xw (s0)
    cudaEventRecord(eJoin, sB);
    cudaStreamWaitEvent(0, eJoin, 0);

    // ---- hop 1 tail + hop 2 (stream 0) ----
    k_agg<<<AGB, 256>>>();
    k_final<<<GT, 128>>>(p_h, g1_w, g1_b, p_xhat, p_xcur, out, 1, NN);
    k_dual<<<GT, 128>>>(p_xcur, gat2_w, lin2_w, lin2_b, id_emb, p_xw, p_xhat, NN);
    k_agg<<<AGB, 256>>>();
    k_final<<<GT, 128>>>(p_h, g2_w, g2_b, p_xhat, p_x, out + 64, 0, NN);
}

// round 15
// speedup vs baseline: 1.2070x; 1.0669x over previous
#include <cuda_runtime.h>
#include <math.h>

#define NI 80000
#define NU 20000
#define NN 100000
#define EE 1000000

// ---------------- scratch (static device globals; no allocs) ----------------
__device__ float g_x[NN * 64];
__device__ float g_xw[NN * 64];
__device__ float g_h[NN * 64];
__device__ float g_xhat[NN * 64];
__device__ float g_xcur[NN * 64];
__device__ int   g_cnt[NN];
__device__ int   g_deg[NN];
__device__ int   g_start[NN + 1];
__device__ int   g_cursor[NN];
__device__ int   g_csr[EE];
__device__ float g_dinv[NN];
__device__ int   g_bsum[128];

__device__ __forceinline__ float leaky(float v) { return v >= 0.f ? v : 0.01f * v; }

__device__ __forceinline__ unsigned long long packdup(float a) {
    unsigned long long r;
    asm("mov.b64 %0, {%1, %1};" : "=l"(r) : "f"(a));
    return r;
}
__device__ __forceinline__ void ffma2(unsigned long long& d, unsigned long long a,
                                      unsigned long long b) {
    asm("fma.rn.f32x2 %0, %1, %2, %0;" : "+l"(d) : "l"(a), "l"(b));
}
__device__ __forceinline__ float2 unpack2(unsigned long long v) {
    float2 f;
    asm("mov.b64 {%0, %1}, %2;" : "=f"(f.x), "=f"(f.y) : "l"(v));
    return f;
}

// ---------------- zero counters ----------------
__global__ void k_zero() {
    int i = blockIdx.x * blockDim.x + threadIdx.x;
    if (i < NN) { g_cnt[i] = 0; g_deg[i] = 0; }
}

// ---------------- build x (items + users) ----------
#define ITEM_B (NI / 8)
#define USER_B 592
__global__ void __launch_bounds__(256) k_build(const float* __restrict__ f,
                                               const float* __restrict__ uf,
                                               const float* __restrict__ Wu,
                                               const float* __restrict__ bu) {
    __shared__ __align__(16) float ws[128 * 64];
    int tid = threadIdx.x;

    if (blockIdx.x < ITEM_B) {
        int w = blockIdx.x * 8 + (tid >> 5);
        int lane = tid & 31;
        float2 v = *reinterpret_cast<const float2*>(f + (size_t)w * 64 + 2 * lane);
        float ss = v.x * v.x + v.y * v.y;
        ss += __shfl_xor_sync(0xffffffffu, ss, 16);
        ss += __shfl_xor_sync(0xffffffffu, ss, 8);
        ss += __shfl_xor_sync(0xffffffffu, ss, 4);
        ss += __shfl_xor_sync(0xffffffffu, ss, 2);
        ss += __shfl_xor_sync(0xffffffffu, ss, 1);
        float sc = __fdividef(1.f, fmaxf(sqrtf(ss), 1e-12f));
        *reinterpret_cast<float2*>(g_x + (size_t)w * 64 + 2 * lane) =
            make_float2(v.x * sc, v.y * sc);
        return;
    }
    int ub = blockIdx.x - ITEM_B;
    for (int i = tid; i < 8192; i += 256) {
        int c = i >> 7, k = i & 127;
        ws[k * 64 + c] = Wu[i];
    }
    __syncthreads();
    int lane = tid & 31, wp = tid >> 5;
    for (int u = ub * 8 + wp; u < NU; u += USER_B * 8) {
        float4 my = *reinterpret_cast<const float4*>(uf + (size_t)u * 128 + lane * 4);
        float a0 = bu[2 * lane], a1 = bu[2 * lane + 1];
        for (int sl = 0; sl < 32; sl++) {
            float v0 = __shfl_sync(0xffffffffu, my.x, sl);
            float v1 = __shfl_sync(0xffffffffu, my.y, sl);
            float v2 = __shfl_sync(0xffffffffu, my.z, sl);
            float v3 = __shfl_sync(0xffffffffu, my.w, sl);
            int k0 = sl * 4;
            float2 w;
            w = *reinterpret_cast<const float2*>(&ws[(k0 + 0) * 64 + 2 * lane]);
            a0 = fmaf(v0, w.x, a0); a1 = fmaf(v0, w.y, a1);
            w = *reinterpret_cast<const float2*>(&ws[(k0 + 1) * 64 + 2 * lane]);
            a0 = fmaf(v1, w.x, a0); a1 = fmaf(v1, w.y, a1);
            w = *reinterpret_cast<const float2*>(&ws[(k0 + 2) * 64 + 2 * lane]);
            a0 = fmaf(v2, w.x, a0); a1 = fmaf(v2, w.y, a1);
            w = *reinterpret_cast<const float2*>(&ws[(k0 + 3) * 64 + 2 * lane]);
            a0 = fmaf(v3, w.x, a0); a1 = fmaf(v3, w.y, a1);
        }
        float t0 = tanhf(a0), t1 = tanhf(a1);
        float ss = t0 * t0 + t1 * t1;
        ss += __shfl_xor_sync(0xffffffffu, ss, 16);
        ss += __shfl_xor_sync(0xffffffffu, ss, 8);
        ss += __shfl_xor_sync(0xffffffffu, ss, 4);
        ss += __shfl_xor_sync(0xffffffffu, ss, 2);
        ss += __shfl_xor_sync(0xffffffffu, ss, 1);
        float sc = __fdividef(1.f, fmaxf(sqrtf(ss), 1e-12f));
        *reinterpret_cast<float2*>(g_x + (size_t)(NI + u) * 64 + 2 * lane) =
            make_float2(t0 * sc, t1 * sc);
    }
}

// ---------------- preprocessing ----------------
__global__ void k_hist(const int* __restrict__ src, const int* __restrict__ dst, int E) {
    int i = blockIdx.x * blockDim.x + threadIdx.x;
    if (i < E) {
        atomicAdd(&g_cnt[dst[i]], 1);
        atomicAdd(&g_deg[src[i]], 1);
    }
}

__global__ void k_scan1() {
    __shared__ int sd[1024];
    int t = threadIdx.x;
    int idx = blockIdx.x * 1024 + t;
    int v = (idx < NN) ? g_cnt[idx] : 0;
    sd[t] = v;
    __syncthreads();
    for (int off = 1; off < 1024; off <<= 1) {
        int add = (t >= off) ? sd[t - off] : 0;
        __syncthreads();
        sd[t] += add;
        __syncthreads();
    }
    if (idx < NN) g_start[idx + 1] = sd[t];
    if (t == 0) g_bsum[blockIdx.x] = sd[1023];
}

__global__ void k_scan23(int nb) {
    __shared__ int s[128];
    int t = threadIdx.x;
    if (t < 128) s[t] = (t < nb) ? g_bsum[t] : 0;
    __syncthreads();
    for (int off = 1; off < 128; off <<= 1) {
        int add = (t >= off && t < 128) ? s[t - off] : 0;
        __syncthreads();
        if (t < 128) s[t] += add;
        __syncthreads();
    }
    int boff = (blockIdx.x == 0) ? 0 : s[blockIdx.x - 1];
    int idx = blockIdx.x * 1024 + t;
    if (idx < NN) {
        int v = g_start[idx + 1] + boff;
        g_start[idx + 1] = v;
        if (idx + 1 < NN) g_cursor[idx + 1] = v;
        int d = g_deg[idx];
        g_dinv[idx] = (d > 0) ? rsqrtf((float)d) : 0.f;
    }
    if (idx == 0) { g_start[0] = 0; g_cursor[0] = 0; }
}

__global__ void k_scatter(const int* __restrict__ src, const int* __restrict__ dst, int E) {
    int i = blockIdx.x * blockDim.x + threadIdx.x;
    if (i < E) {
        int d = dst[i];
        int p = atomicAdd(&g_cursor[d], 1);
        g_csr[p] = src[i];
    }
}

// ======================= GEMM core (8 rows x 8 cols / thread, 128 thr) ==========
struct Acc8x4 { unsigned long long a[8][4]; };

__device__ __forceinline__ void gemm_pass(const float* __restrict__ xs,
                                          const float* __restrict__ ws,
                                          int rg, int c0, int swz, Acc8x4& A) {
#pragma unroll
    for (int rr = 0; rr < 8; rr++)
#pragma unroll
        for (int p = 0; p < 4; p++) A.a[rr][p] = 0ull;
#pragma unroll 4
    for (int kb = 0; kb < 64; kb += 4) {
        float4 a4[8];
#pragma unroll
        for (int rr = 0; rr < 8; rr++)
            a4[rr] = *(const float4*)&xs[(rg * 8 + rr) * 64 + (kb ^ swz)];
#pragma unroll
        for (int j = 0; j < 4; j++) {
            int k = kb + j;
            ulonglong2 wA = *(const ulonglong2*)&ws[k * 64 + c0];
            ulonglong2 wB = *(const ulonglong2*)&ws[k * 64 + c0 + 4];
#pragma unroll
            for (int rr = 0; rr < 8; rr++) {
                float a = (j == 0) ? a4[rr].x : (j == 1) ? a4[rr].y
                          : (j == 2) ? a4[rr].z : a4[rr].w;
                unsigned long long aa = packdup(a);
                ffma2(A.a[rr][0], aa, wA.x); ffma2(A.a[rr][1], aa, wA.y);
                ffma2(A.a[rr][2], aa, wB.x); ffma2(A.a[rr][3], aa, wB.y);
            }
        }
    }
}

__device__ __forceinline__ void load_xs(float* __restrict__ xs,
                                        const float* __restrict__ in,
                                        int row0, int n, int tid) {
    for (int i = tid * 4; i < 8192; i += 512) {
        int r = i >> 6, k = i & 63;
        int sw = ((r >> 3) & 7) * 8;
        int gr = row0 + r;
        float4 v = (gr < n) ? *(const float4*)(in + (size_t)gr * 64 + k)
                            : make_float4(0.f, 0.f, 0.f, 0.f);
        *(float4*)&xs[r * 64 + (k ^ sw)] = v;
    }
}

// ---------------- gat GEMM: xw = in@Wg (no epilogue) ----------------
__global__ void __launch_bounds__(128, 4) k_gat(const float* __restrict__ in,
                                                const float* __restrict__ Wg,
                                                float* __restrict__ xw, int n) {
    __shared__ __align__(16) float ws[4096];
    __shared__ __align__(16) float xs[8192];
    int tid = threadIdx.x;
    int rg = tid >> 3, cg = tid & 7;
    int c0 = cg * 8;
    int swz = (rg & 7) * 8;
    int row0 = blockIdx.x * 128;

    for (int i = tid; i < 4096; i += 128) ws[i] = Wg[i];   // direct [k][c]
    load_xs(xs, in, row0, n, tid);
    __syncthreads();

    Acc8x4 A;
    gemm_pass(xs, ws, rg, c0, swz, A);
#pragma unroll
    for (int rr = 0; rr < 8; rr++) {
        int r = row0 + rg * 8 + rr;
        if (r < n) {
            size_t base = (size_t)r * 64 + c0;
            float2 v0 = unpack2(A.a[rr][0]), v1 = unpack2(A.a[rr][1]);
            float2 v2 = unpack2(A.a[rr][2]), v3 = unpack2(A.a[rr][3]);
            *(float4*)(xw + base) = make_float4(v0.x, v0.y, v1.x, v1.y);
            *(float4*)(xw + base + 4) = make_float4(v2.x, v2.y, v3.x, v3.y);
        }
    }
}

// ---------------- lin GEMM: xhat = leaky(in@Wl' + b) + id ----------------
__global__ void __launch_bounds__(128, 4) k_lin(const float* __restrict__ in,
                                                const float* __restrict__ Wl,
                                                const float* __restrict__ bias,
                                                const float* __restrict__ idw,
                                                float* __restrict__ xhat, int n) {
    __shared__ __align__(16) float ws[4096];
    __shared__ __align__(16) float xs[8192];
    int tid = threadIdx.x;
    int rg = tid >> 3, cg = tid & 7;
    int c0 = cg * 8;
    int swz = (rg & 7) * 8;
    int row0 = blockIdx.x * 128;

    for (int i = tid; i < 4096; i += 128) {
        int k = i >> 6, c = i & 63;
        ws[i] = Wl[c * 64 + k];   // transposed
    }
    load_xs(xs, in, row0, n, tid);
    __syncthreads();

    Acc8x4 A;
    gemm_pass(xs, ws, rg, c0, swz, A);
    float4 b0 = *(const float4*)(bias + c0);
    float4 b1 = *(const float4*)(bias + c0 + 4);
#pragma unroll
    for (int rr = 0; rr < 8; rr++) {
        int r = row0 + rg * 8 + rr;
        if (r < n) {
            size_t base = (size_t)r * 64 + c0;
            float2 u0 = unpack2(A.a[rr][0]), u1 = unpack2(A.a[rr][1]);
            float2 u2 = unpack2(A.a[rr][2]), u3 = unpack2(A.a[rr][3]);
            float4 i0 = *(const float4*)(idw + base);
            float4 i1 = *(const float4*)(idw + base + 4);
            *(float4*)(xhat + base) = make_float4(
                leaky(u0.x + b0.x) + i0.x, leaky(u0.y + b0.y) + i0.y,
                leaky(u1.x + b0.z) + i0.z, leaky(u1.y + b0.w) + i0.w);
            *(float4*)(xhat + base + 4) = make_float4(
                leaky(u2.x + b1.x) + i1.x, leaky(u2.y + b1.y) + i1.y,
                leaky(u3.x + b1.z) + i1.z, leaky(u3.y + b1.w) + i1.w);
        }
    }
}

// ---------------- final GEMM: v = leaky(h@W' + b + xhat); out2 always, outb opt ----
__global__ void __launch_bounds__(128, 4) k_final(const float* __restrict__ in,
                                                  const float* __restrict__ W,
                                                  const float* __restrict__ bias,
                                                  const float* __restrict__ add,
                                                  float* __restrict__ outb,
                                                  float* __restrict__ out2,
                                                  int write_outb, int n) {
    __shared__ __align__(16) float ws[4096];
    __shared__ __align__(16) float xs[8192];
    int tid = threadIdx.x;
    int rg = tid >> 3, cg = tid & 7;
    int c0 = cg * 8;
    int swz = (rg & 7) * 8;
    int row0 = blockIdx.x * 128;

    for (int i = tid; i < 4096; i += 128) {
        int k = i >> 6, c = i & 63;
        ws[i] = W[c * 64 + k];
    }
    load_xs(xs, in, row0, n, tid);
    __syncthreads();

    Acc8x4 A;
    gemm_pass(xs, ws, rg, c0, swz, A);
    float4 b0 = *(const float4*)(bias + c0);
    float4 b1 = *(const float4*)(bias + c0 + 4);
#pragma unroll
    for (int rr = 0; rr < 8; rr++) {
        int r = row0 + rg * 8 + rr;
        if (r < n) {
            size_t base = (size_t)r * 64 + c0;
            float2 u0 = unpack2(A.a[rr][0]), u1 = unpack2(A.a[rr][1]);
            float2 u2 = unpack2(A.a[rr][2]), u3 = unpack2(A.a[rr][3]);
            float4 h0 = *(const float4*)(add + base);
            float4 h1 = *(const float4*)(add + base + 4);
            float4 o0 = make_float4(leaky(u0.x + b0.x + h0.x), leaky(u0.y + b0.y + h0.y),
                                    leaky(u1.x + b0.z + h0.z), leaky(u1.y + b0.w + h0.w));
            float4 o1 = make_float4(leaky(u2.x + b1.x + h1.x), leaky(u2.y + b1.y + h1.y),
                                    leaky(u3.x + b1.z + h1.z), leaky(u3.y + b1.w + h1.w));
            if (write_outb) {
                *(float4*)(outb + base) = o0;
                *(float4*)(outb + base + 4) = o1;
            }
            *(float4*)(out2 + (size_t)r * 128 + c0) = o0;
            *(float4*)(out2 + (size_t)r * 128 + c0 + 4) = o1;
        }
    }
}

// ---------------- GAT aggregation: 2 nodes/warp (16 lanes each), no-max softmax ----
__global__ void __launch_bounds__(256) k_agg() {
    int gw = (blockIdx.x * blockDim.x + threadIdx.x) >> 5;
    int lane = threadIdx.x & 31;
    int half = lane >> 4;
    int hl = lane & 15;
    int w = gw * 2 + half;
    bool valid = (w < NN);
    int s = 0, cnt = 0;
    if (valid) { s = g_start[w]; cnt = g_start[w + 1] - s; }
    float4 xv = make_float4(0.f, 0.f, 0.f, 0.f);
    if (valid) xv = *(const float4*)(g_xw + (size_t)w * 64 + hl * 4);
    int cntmax = max(cnt, __shfl_xor_sync(0xffffffffu, cnt, 16));
    const float NEGINF = __int_as_float(0xff800000);
    float z = 0.f;
    float4 acc = make_float4(0.f, 0.f, 0.f, 0.f);
    int u_l = 0; float dv_l = 0.f;
    if (hl < cnt) { u_l = g_csr[s + hl]; dv_l = g_dinv[u_l]; }
    int hbase = half << 4;
    for (int i = 0; i < cntmax; i += 2) {
        int j = i & 15;
        if (j == 0 && i > 0) {
            int idx = i + hl;
            u_l = (idx < cnt) ? g_csr[s + idx] : 0;
            dv_l = (idx < cnt) ? g_dinv[u_l] : 0.f;
        }
        int u0 = __shfl_sync(0xffffffffu, u_l, hbase + j);
        int u1 = __shfl_sync(0xffffffffu, u_l, hbase + j + 1);
        float dv0 = __shfl_sync(0xffffffffu, dv_l, hbase + j);
        float dv1 = __shfl_sync(0xffffffffu, dv_l, hbase + j + 1);
        float4 a0 = *(const float4*)(g_xw + (size_t)u0 * 64 + hl * 4);
        float4 a1 = *(const float4*)(g_xw + (size_t)u1 * 64 + hl * 4);
        float p0 = fmaf(xv.x, a0.x, fmaf(xv.y, a0.y, fmaf(xv.z, a0.z, xv.w * a0.w)));
        float p1 = fmaf(xv.x, a1.x, fmaf(xv.y, a1.y, fmaf(xv.z, a1.z, xv.w * a1.w)));
#pragma unroll
        for (int o = 8; o; o >>= 1) {
            p0 += __shfl_xor_sync(0xffffffffu, p0, o);
            p1 += __shfl_xor_sync(0xffffffffu, p1, o);
        }
        float lg0 = (i < cnt) ? p0 * __fdividef(1.f, 1.f + __expf(-p0 * dv0)) : NEGINF;
        float lg1 = (i + 1 < cnt) ? p1 * __fdividef(1.f, 1.f + __expf(-p1 * dv1)) : NEGINF;
        float pe0 = __expf(lg0);
        float pe1 = __expf(lg1);
        z += pe0 + pe1;
        acc.x += fmaf(pe0, a0.x, pe1 * a1.x);
        acc.y += fmaf(pe0, a0.y, pe1 * a1.y);
        acc.z += fmaf(pe0, a0.z, pe1 * a1.z);
        acc.w += fmaf(pe0, a0.w, pe1 * a1.w);
    }
    if (valid) {
        float inv = __fdividef(1.f, z + 1e-16f);
        *(float4*)(g_h + (size_t)w * 64 + hl * 4) =
            make_float4(leaky(acc.x * inv), leaky(acc.y * inv),
                        leaky(acc.z * inv), leaky(acc.w * inv));
    }
}

// ---------------- launch ----------------
extern "C" void kernel_launch(void* const* d_in, const int* in_sizes, int n_in,
                              void* d_out, int out_size) {
    const float* features = (const float*)d_in[0];
    const float* user_features = (const float*)d_in[1];
    const float* id_emb = (const float*)d_in[2];
    const float* user_mlp_w = (const float*)d_in[3];
    const float* user_mlp_b = (const float*)d_in[4];
    const float* gat1_w = (const float*)d_in[5];
    const float* lin1_w = (const float*)d_in[6];
    const float* lin1_b = (const float*)d_in[7];
    const float* g1_w = (const float*)d_in[8];
    const float* g1_b = (const float*)d_in[9];
    const float* gat2_w = (const float*)d_in[10];
    const float* lin2_w = (const float*)d_in[11];
    const float* lin2_b = (const float*)d_in[12];
    const float* g2_w = (const float*)d_in[13];
    const float* g2_b = (const float*)d_in[14];
    const int* edge_index = (const int*)d_in[15];
    float* out = (float*)d_out;

    int E = in_sizes[15] / 2;
    if (E > EE) E = EE;
    const int* src = edge_index;
    const int* dst = edge_index + E;

    float *p_x, *p_xw, *p_h, *p_xhat, *p_xcur;
    cudaGetSymbolAddress((void**)&p_x, g_x);
    cudaGetSymbolAddress((void**)&p_xw, g_xw);
    cudaGetSymbolAddress((void**)&p_h, g_h);
    cudaGetSymbolAddress((void**)&p_xhat, g_xhat);
    cudaGetSymbolAddress((void**)&p_xcur, g_xcur);

    int gn = (NN + 255) / 256;
    int ge = (E + 255) / 256;
    int nb = (NN + 1023) / 1024;
    const int GT = (NN + 127) / 128;
    const int AGB = (NN / 2 + 7) / 8;

    static cudaStream_t sB = nullptr;
    static cudaEvent_t eFork = nullptr, eBuild = nullptr, eJoin = nullptr;
    static cudaEvent_t eLin1 = nullptr, eF1 = nullptr, eLin2 = nullptr;
    if (sB == nullptr) {
        cudaStreamCreateWithFlags(&sB, cudaStreamNonBlocking);
        cudaEventCreateWithFlags(&eFork, cudaEventDisableTiming);
        cudaEventCreateWithFlags(&eBuild, cudaEventDisableTiming);
        cudaEventCreateWithFlags(&eJoin, cudaEventDisableTiming);
        cudaEventCreateWithFlags(&eLin1, cudaEventDisableTiming);
        cudaEventCreateWithFlags(&eF1, cudaEventDisableTiming);
        cudaEventCreateWithFlags(&eLin2, cudaEventDisableTiming);
    }

    // fork
    cudaEventRecord(eFork, 0);
    cudaStreamWaitEvent(sB, eFork, 0);

    // sB: zero -> hist -> scan -> scatter -> lin1 (after eBuild)
    // s0: build -> gat1 -> (wait eJoin) agg1 -> (wait eLin1) final1 -> ...
    k_zero<<<gn, 256, 0, sB>>>();                                        // 1
    k_build<<<ITEM_B + USER_B, 256>>>(features, user_features,           // 2
                                      user_mlp_w, user_mlp_b);
    cudaEventRecord(eBuild, 0);
    k_hist<<<ge, 256, 0, sB>>>(src, dst, E);                             // 3
    k_gat<<<GT, 128>>>(p_x, gat1_w, p_xw, NN);                           // 4 (profiled)
    k_scan1<<<nb, 1024, 0, sB>>>();                                      // 5
    k_scan23<<<nb, 1024, 0, sB>>>(nb);                                   // 6
    k_scatter<<<ge, 256, 0, sB>>>(src, dst, E);                          // 7
    cudaEventRecord(eJoin, sB);
    cudaStreamWaitEvent(sB, eBuild, 0);
    k_lin<<<GT, 128, 0, sB>>>(p_x, lin1_w, lin1_b, id_emb, p_xhat, NN);  // 8
    cudaEventRecord(eLin1, sB);

    cudaStreamWaitEvent(0, eJoin, 0);
    k_agg<<<AGB, 256>>>();                                               // 9
    cudaStreamWaitEvent(0, eLin1, 0);
    k_final<<<GT, 128>>>(p_h, g1_w, g1_b, p_xhat, p_xcur, out, 1, NN);   // 10
    cudaEventRecord(eF1, 0);

    // hop 2: lin2 on sB concurrent with gat2+agg2 on s0
    cudaStreamWaitEvent(sB, eF1, 0);
    k_lin<<<GT, 128, 0, sB>>>(p_xcur, lin2_w, lin2_b, id_emb, p_xhat, NN);  // 11
    cudaEventRecord(eLin2, sB);

    k_gat<<<GT, 128>>>(p_xcur, gat2_w, p_xw, NN);                        // 12
    k_agg<<<AGB, 256>>>();                                               // 13
    cudaStreamWaitEvent(0, eLin2, 0);
    k_final<<<GT, 128>>>(p_h, g2_w, g2_b, p_xhat, p_x, out + 64, 0, NN); // 14
}

// round 16
// speedup vs baseline: 1.2139x; 1.0057x over previous
#include <cuda_runtime.h>
#include <math.h>

#define NI 80000
#define NU 20000
#define NN 100000
#define EE 1000000

// ---------------- scratch (static device globals; no allocs) ----------------
__device__ float g_x[NN * 64];
__device__ float g_xw[NN * 64];
__device__ float g_h[NN * 64];
__device__ float g_xhat[NN * 64];
__device__ float g_xcur[NN * 64];
__device__ int   g_cnt[NN];
__device__ int   g_deg[NN];
__device__ int   g_start[NN + 1];
__device__ int   g_cursor[NN];
__device__ int   g_csr[EE];
__device__ float g_csrdv[EE];
__device__ float g_dinv[NN];
__device__ int   g_bsum[128];

__device__ __forceinline__ float leaky(float v) { return v >= 0.f ? v : 0.01f * v; }

__device__ __forceinline__ unsigned long long packdup(float a) {
    unsigned long long r;
    asm("mov.b64 %0, {%1, %1};" : "=l"(r) : "f"(a));
    return r;
}
__device__ __forceinline__ void ffma2(unsigned long long& d, unsigned long long a,
                                      unsigned long long b) {
    asm("fma.rn.f32x2 %0, %1, %2, %0;" : "+l"(d) : "l"(a), "l"(b));
}
__device__ __forceinline__ float2 unpack2(unsigned long long v) {
    float2 f;
    asm("mov.b64 {%0, %1}, %2;" : "=f"(f.x), "=f"(f.y) : "l"(v));
    return f;
}

// ---------------- zero counters ----------------
__global__ void k_zero() {
    int i = blockIdx.x * blockDim.x + threadIdx.x;
    if (i < NN) { g_cnt[i] = 0; g_deg[i] = 0; }
}

// ---------------- build x (items + users) ----------
#define ITEM_B (NI / 8)
#define USER_B 592
__global__ void __launch_bounds__(256) k_build(const float* __restrict__ f,
                                               const float* __restrict__ uf,
                                               const float* __restrict__ Wu,
                                               const float* __restrict__ bu) {
    __shared__ __align__(16) float ws[128 * 64];
    int tid = threadIdx.x;

    if (blockIdx.x < ITEM_B) {
        int w = blockIdx.x * 8 + (tid >> 5);
        int lane = tid & 31;
        float2 v = *reinterpret_cast<const float2*>(f + (size_t)w * 64 + 2 * lane);
        float ss = v.x * v.x + v.y * v.y;
        ss += __shfl_xor_sync(0xffffffffu, ss, 16);
        ss += __shfl_xor_sync(0xffffffffu, ss, 8);
        ss += __shfl_xor_sync(0xffffffffu, ss, 4);
        ss += __shfl_xor_sync(0xffffffffu, ss, 2);
        ss += __shfl_xor_sync(0xffffffffu, ss, 1);
        float sc = __fdividef(1.f, fmaxf(sqrtf(ss), 1e-12f));
        *reinterpret_cast<float2*>(g_x + (size_t)w * 64 + 2 * lane) =
            make_float2(v.x * sc, v.y * sc);
        return;
    }
    int ub = blockIdx.x - ITEM_B;
    for (int i = tid; i < 8192; i += 256) {
        int c = i >> 7, k = i & 127;
        ws[k * 64 + c] = Wu[i];
    }
    __syncthreads();
    int lane = tid & 31, wp = tid >> 5;
    for (int u = ub * 8 + wp; u < NU; u += USER_B * 8) {
        float4 my = *reinterpret_cast<const float4*>(uf + (size_t)u * 128 + lane * 4);
        float a0 = bu[2 * lane], a1 = bu[2 * lane + 1];
        for (int sl = 0; sl < 32; sl++) {
            float v0 = __shfl_sync(0xffffffffu, my.x, sl);
            float v1 = __shfl_sync(0xffffffffu, my.y, sl);
            float v2 = __shfl_sync(0xffffffffu, my.z, sl);
            float v3 = __shfl_sync(0xffffffffu, my.w, sl);
            int k0 = sl * 4;
            float2 w;
            w = *reinterpret_cast<const float2*>(&ws[(k0 + 0) * 64 + 2 * lane]);
            a0 = fmaf(v0, w.x, a0); a1 = fmaf(v0, w.y, a1);
            w = *reinterpret_cast<const float2*>(&ws[(k0 + 1) * 64 + 2 * lane]);
            a0 = fmaf(v1, w.x, a0); a1 = fmaf(v1, w.y, a1);
            w = *reinterpret_cast<const float2*>(&ws[(k0 + 2) * 64 + 2 * lane]);
            a0 = fmaf(v2, w.x, a0); a1 = fmaf(v2, w.y, a1);
            w = *reinterpret_cast<const float2*>(&ws[(k0 + 3) * 64 + 2 * lane]);
            a0 = fmaf(v3, w.x, a0); a1 = fmaf(v3, w.y, a1);
        }
        float t0 = tanhf(a0), t1 = tanhf(a1);
        float ss = t0 * t0 + t1 * t1;
        ss += __shfl_xor_sync(0xffffffffu, ss, 16);
        ss += __shfl_xor_sync(0xffffffffu, ss, 8);
        ss += __shfl_xor_sync(0xffffffffu, ss, 4);
        ss += __shfl_xor_sync(0xffffffffu, ss, 2);
        ss += __shfl_xor_sync(0xffffffffu, ss, 1);
        float sc = __fdividef(1.f, fmaxf(sqrtf(ss), 1e-12f));
        *reinterpret_cast<float2*>(g_x + (size_t)(NI + u) * 64 + 2 * lane) =
            make_float2(t0 * sc, t1 * sc);
    }
}

// ---------------- preprocessing ----------------
__global__ void k_hist(const int* __restrict__ src, const int* __restrict__ dst, int E) {
    int i = blockIdx.x * blockDim.x + threadIdx.x;
    if (i < E) {
        atomicAdd(&g_cnt[dst[i]], 1);
        atomicAdd(&g_deg[src[i]], 1);
    }
}

__global__ void k_scan1() {
    __shared__ int sd[1024];
    int t = threadIdx.x;
    int idx = blockIdx.x * 1024 + t;
    int v = (idx < NN) ? g_cnt[idx] : 0;
    sd[t] = v;
    __syncthreads();
    for (int off = 1; off < 1024; off <<= 1) {
        int add = (t >= off) ? sd[t - off] : 0;
        __syncthreads();
        sd[t] += add;
        __syncthreads();
    }
    if (idx < NN) g_start[idx + 1] = sd[t];
    if (t == 0) g_bsum[blockIdx.x] = sd[1023];
}

__global__ void k_scan23(int nb) {
    __shared__ int s[128];
    int t = threadIdx.x;
    if (t < 128) s[t] = (t < nb) ? g_bsum[t] : 0;
    __syncthreads();
    for (int off = 1; off < 128; off <<= 1) {
        int add = (t >= off && t < 128) ? s[t - off] : 0;
        __syncthreads();
        if (t < 128) s[t] += add;
        __syncthreads();
    }
    int boff = (blockIdx.x == 0) ? 0 : s[blockIdx.x - 1];
    int idx = blockIdx.x * 1024 + t;
    if (idx < NN) {
        int v = g_start[idx + 1] + boff;
        g_start[idx + 1] = v;
        if (idx + 1 < NN) g_cursor[idx + 1] = v;
        int d = g_deg[idx];
        g_dinv[idx] = (d > 0) ? rsqrtf((float)d) : 0.f;
    }
    if (idx == 0) { g_start[0] = 0; g_cursor[0] = 0; }
}

__global__ void k_scatter(const int* __restrict__ src, const int* __restrict__ dst, int E) {
    int i = blockIdx.x * blockDim.x + threadIdx.x;
    if (i < E) {
        int sv = src[i];
        int d = dst[i];
        int p = atomicAdd(&g_cursor[d], 1);
        g_csr[p] = sv;
        g_csrdv[p] = g_dinv[sv];
    }
}

// ======================= GEMM core (8 rows x 8 cols / thread, 128 thr) ==========
struct Acc8x4 { unsigned long long a[8][4]; };

__device__ __forceinline__ void gemm_pass(const float* __restrict__ xs,
                                          const float* __restrict__ ws,
                                          int rg, int c0, int swz, Acc8x4& A) {
#pragma unroll
    for (int rr = 0; rr < 8; rr++)
#pragma unroll
        for (int p = 0; p < 4; p++) A.a[rr][p] = 0ull;
#pragma unroll 4
    for (int kb = 0; kb < 64; kb += 4) {
        float4 a4[8];
#pragma unroll
        for (int rr = 0; rr < 8; rr++)
            a4[rr] = *(const float4*)&xs[(rg * 8 + rr) * 64 + (kb ^ swz)];
#pragma unroll
        for (int j = 0; j < 4; j++) {
            int k = kb + j;
            ulonglong2 wA = *(const ulonglong2*)&ws[k * 64 + c0];
            ulonglong2 wB = *(const ulonglong2*)&ws[k * 64 + c0 + 4];
#pragma unroll
            for (int rr = 0; rr < 8; rr++) {
                float a = (j == 0) ? a4[rr].x : (j == 1) ? a4[rr].y
                          : (j == 2) ? a4[rr].z : a4[rr].w;
                unsigned long long aa = packdup(a);
                ffma2(A.a[rr][0], aa, wA.x); ffma2(A.a[rr][1], aa, wA.y);
                ffma2(A.a[rr][2], aa, wB.x); ffma2(A.a[rr][3], aa, wB.y);
            }
        }
    }
}

__device__ __forceinline__ void load_xs(float* __restrict__ xs,
                                        const float* __restrict__ in,
                                        int row0, int n, int tid) {
    for (int i = tid * 4; i < 8192; i += 512) {
        int r = i >> 6, k = i & 63;
        int sw = ((r >> 3) & 7) * 8;
        int gr = row0 + r;
        float4 v = (gr < n) ? *(const float4*)(in + (size_t)gr * 64 + k)
                            : make_float4(0.f, 0.f, 0.f, 0.f);
        *(float4*)&xs[r * 64 + (k ^ sw)] = v;
    }
}

// ---------------- gat GEMM: xw = in@Wg (no epilogue) ----------------
__global__ void __launch_bounds__(128, 4) k_gat(const float* __restrict__ in,
                                                const float* __restrict__ Wg,
                                                float* __restrict__ xw, int n) {
    __shared__ __align__(16) float ws[4096];
    __shared__ __align__(16) float xs[8192];
    int tid = threadIdx.x;
    int rg = tid >> 3, cg = tid & 7;
    int c0 = cg * 8;
    int swz = (rg & 7) * 8;
    int row0 = blockIdx.x * 128;

    for (int i = tid; i < 4096; i += 128) ws[i] = Wg[i];
    load_xs(xs, in, row0, n, tid);
    __syncthreads();

    Acc8x4 A;
    gemm_pass(xs, ws, rg, c0, swz, A);
#pragma unroll
    for (int rr = 0; rr < 8; rr++) {
        int r = row0 + rg * 8 + rr;
        if (r < n) {
            size_t base = (size_t)r * 64 + c0;
            float2 v0 = unpack2(A.a[rr][0]), v1 = unpack2(A.a[rr][1]);
            float2 v2 = unpack2(A.a[rr][2]), v3 = unpack2(A.a[rr][3]);
            *(float4*)(xw + base) = make_float4(v0.x, v0.y, v1.x, v1.y);
            *(float4*)(xw + base + 4) = make_float4(v2.x, v2.y, v3.x, v3.y);
        }
    }
}

// ---------------- lin GEMM: xhat = leaky(in@Wl' + b) + id ----------------
__global__ void __launch_bounds__(128, 4) k_lin(const float* __restrict__ in,
                                                const float* __restrict__ Wl,
                                                const float* __restrict__ bias,
                                                const float* __restrict__ idw,
                                                float* __restrict__ xhat, int n) {
    __shared__ __align__(16) float ws[4096];
    __shared__ __align__(16) float xs[8192];
    int tid = threadIdx.x;
    int rg = tid >> 3, cg = tid & 7;
    int c0 = cg * 8;
    int swz = (rg & 7) * 8;
    int row0 = blockIdx.x * 128;

    for (int i = tid; i < 4096; i += 128) {
        int k = i >> 6, c = i & 63;
        ws[i] = Wl[c * 64 + k];
    }
    load_xs(xs, in, row0, n, tid);
    __syncthreads();

    Acc8x4 A;
    gemm_pass(xs, ws, rg, c0, swz, A);
    float4 b0 = *(const float4*)(bias + c0);
    float4 b1 = *(const float4*)(bias + c0 + 4);
#pragma unroll
    for (int rr = 0; rr < 8; rr++) {
        int r = row0 + rg * 8 + rr;
        if (r < n) {
            size_t base = (size_t)r * 64 + c0;
            float2 u0 = unpack2(A.a[rr][0]), u1 = unpack2(A.a[rr][1]);
            float2 u2 = unpack2(A.a[rr][2]), u3 = unpack2(A.a[rr][3]);
            float4 i0 = *(const float4*)(idw + base);
            float4 i1 = *(const float4*)(idw + base + 4);
            *(float4*)(xhat + base) = make_float4(
                leaky(u0.x + b0.x) + i0.x, leaky(u0.y + b0.y) + i0.y,
                leaky(u1.x + b0.z) + i0.z, leaky(u1.y + b0.w) + i0.w);
            *(float4*)(xhat + base + 4) = make_float4(
                leaky(u2.x + b1.x) + i1.x, leaky(u2.y + b1.y) + i1.y,
                leaky(u3.x + b1.z) + i1.z, leaky(u3.y + b1.w) + i1.w);
        }
    }
}

// ---------------- final GEMM: v = leaky(h@W' + b + xhat); out2 always, outb opt ----
__global__ void __launch_bounds__(128, 4) k_final(const float* __restrict__ in,
                                                  const float* __restrict__ W,
                                                  const float* __restrict__ bias,
                                                  const float* __restrict__ add,
                                                  float* __restrict__ outb,
                                                  float* __restrict__ out2,
                                                  int write_outb, int n) {
    __shared__ __align__(16) float ws[4096];
    __shared__ __align__(16) float xs[8192];
    int tid = threadIdx.x;
    int rg = tid >> 3, cg = tid & 7;
    int c0 = cg * 8;
    int swz = (rg & 7) * 8;
    int row0 = blockIdx.x * 128;

    for (int i = tid; i < 4096; i += 128) {
        int k = i >> 6, c = i & 63;
        ws[i] = W[c * 64 + k];
    }
    load_xs(xs, in, row0, n, tid);
    __syncthreads();

    Acc8x4 A;
    gemm_pass(xs, ws, rg, c0, swz, A);
    float4 b0 = *(const float4*)(bias + c0);
    float4 b1 = *(const float4*)(bias + c0 + 4);
#pragma unroll
    for (int rr = 0; rr < 8; rr++) {
        int r = row0 + rg * 8 + rr;
        if (r < n) {
            size_t base = (size_t)r * 64 + c0;
            float2 u0 = unpack2(A.a[rr][0]), u1 = unpack2(A.a[rr][1]);
            float2 u2 = unpack2(A.a[rr][2]), u3 = unpack2(A.a[rr][3]);
            float4 h0 = *(const float4*)(add + base);
            float4 h1 = *(const float4*)(add + base + 4);
            float4 o0 = make_float4(leaky(u0.x + b0.x + h0.x), leaky(u0.y + b0.y + h0.y),
                                    leaky(u1.x + b0.z + h0.z), leaky(u1.y + b0.w + h0.w));
            float4 o1 = make_float4(leaky(u2.x + b1.x + h1.x), leaky(u2.y + b1.y + h1.y),
                                    leaky(u3.x + b1.z + h1.z), leaky(u3.y + b1.w + h1.w));
            if (write_outb) {
                *(float4*)(outb + base) = o0;
                *(float4*)(outb + base + 4) = o1;
            }
            *(float4*)(out2 + (size_t)r * 128 + c0) = o0;
            *(float4*)(out2 + (size_t)r * 128 + c0 + 4) = o1;
        }
    }
}

// ---------------- GAT aggregation: 4 nodes/warp (8 lanes each), no-max softmax -----
// Group-confined 3-level butterfly + scalar softmax chain amortized over 4 groups
// SIMD-wide. 2 edges per group per iteration. dinv pre-gathered into g_csrdv.
__global__ void __launch_bounds__(256) k_agg() {
    int gw = (blockIdx.x * blockDim.x + threadIdx.x) >> 5;
    int lane = threadIdx.x & 31;
    int g = lane >> 3;       // group 0..3
    int gl = lane & 7;       // lane within group
    int w = gw * 4 + g;      // node; grid sized so w < NN always (NN % 4 == 0)
    int s = g_start[w];
    int cnt = g_start[w + 1] - s;
    const float* xvp = g_xw + (size_t)w * 64 + gl * 8;
    float4 xv0 = *(const float4*)xvp;
    float4 xv1 = *(const float4*)(xvp + 4);
    int cntmax = cnt;
    cntmax = max(cntmax, __shfl_xor_sync(0xffffffffu, cntmax, 8));
    cntmax = max(cntmax, __shfl_xor_sync(0xffffffffu, cntmax, 16));
    const float NEGINF = __int_as_float(0xff800000);
    float z = 0.f;
    float4 acc0 = make_float4(0.f, 0.f, 0.f, 0.f);
    float4 acc1 = make_float4(0.f, 0.f, 0.f, 0.f);
    int u_l = 0; float dv_l = 0.f;
    if (gl < cnt) { u_l = g_csr[s + gl]; dv_l = g_csrdv[s + gl]; }
    int gbase = g << 3;
    for (int i = 0; i < cntmax; i += 2) {
        int j = i & 7;
        if (j == 0 && i > 0) {
            int idx = i + gl;
            bool vv = idx < cnt;
            u_l = vv ? g_csr[s + idx] : 0;
            dv_l = vv ? g_csrdv[s + idx] : 0.f;
        }
        int u0 = __shfl_sync(0xffffffffu, u_l, gbase + j);
        int u1 = __shfl_sync(0xffffffffu, u_l, gbase + j + 1);
        float dv0 = __shfl_sync(0xffffffffu, dv_l, gbase + j);
        float dv1 = __shfl_sync(0xffffffffu, dv_l, gbase + j + 1);
        const float* r0 = g_xw + (size_t)u0 * 64 + gl * 8;
        const float* r1 = g_xw + (size_t)u1 * 64 + gl * 8;
        float4 a00 = *(const float4*)r0;
        float4 a01 = *(const float4*)(r0 + 4);
        float4 a10 = *(const float4*)r1;
        float4 a11 = *(const float4*)(r1 + 4);
        float p0 = fmaf(xv0.x, a00.x, fmaf(xv0.y, a00.y,
                   fmaf(xv0.z, a00.z, fmaf(xv0.w, a00.w,
                   fmaf(xv1.x, a01.x, fmaf(xv1.y, a01.y,
                   fmaf(xv1.z, a01.z, xv1.w * a01.w)))))));
        float p1 = fmaf(xv0.x, a10.x, fmaf(xv0.y, a10.y,
                   fmaf(xv0.z, a10.z, fmaf(xv0.w, a10.w,
                   fmaf(xv1.x, a11.x, fmaf(xv1.y, a11.y,
                   fmaf(xv1.z, a11.z, xv1.w * a11.w)))))));
#pragma unroll
        for (int o = 4; o; o >>= 1) {
            p0 += __shfl_xor_sync(0xffffffffu, p0, o);
            p1 += __shfl_xor_sync(0xffffffffu, p1, o);
        }
        float lg0 = (i < cnt) ? p0 * __fdividef(1.f, 1.f + __expf(-p0 * dv0)) : NEGINF;
        float lg1 = (i + 1 < cnt) ? p1 * __fdividef(1.f, 1.f + __expf(-p1 * dv1)) : NEGINF;
        float pe0 = __expf(lg0);   // 0 for masked edges (no-max: logits small)
        float pe1 = __expf(lg1);
        z += pe0 + pe1;
        acc0.x = fmaf(pe0, a00.x, fmaf(pe1, a10.x, acc0.x));
        acc0.y = fmaf(pe0, a00.y, fmaf(pe1, a10.y, acc0.y));
        acc0.z = fmaf(pe0, a00.z, fmaf(pe1, a10.z, acc0.z));
        acc0.w = fmaf(pe0, a00.w, fmaf(pe1, a10.w, acc0.w));
        acc1.x = fmaf(pe0, a01.x, fmaf(pe1, a11.x, acc1.x));
        acc1.y = fmaf(pe0, a01.y, fmaf(pe1, a11.y, acc1.y));
        acc1.z = fmaf(pe0, a01.z, fmaf(pe1, a11.z, acc1.z));
        acc1.w = fmaf(pe0, a01.w, fmaf(pe1, a11.w, acc1.w));
    }
    float inv = __fdividef(1.f, z + 1e-16f);
    float* hp = g_h + (size_t)w * 64 + gl * 8;
    *(float4*)hp = make_float4(leaky(acc0.x * inv), leaky(acc0.y * inv),
                               leaky(acc0.z * inv), leaky(acc0.w * inv));
    *(float4*)(hp + 4) = make_float4(leaky(acc1.x * inv), leaky(acc1.y * inv),
                                     leaky(acc1.z * inv), leaky(acc1.w * inv));
}

// ---------------- launch ----------------
extern "C" void kernel_launch(void* const* d_in, const int* in_sizes, int n_in,
                              void* d_out, int out_size) {
    const float* features = (const float*)d_in[0];
    const float* user_features = (const float*)d_in[1];
    const float* id_emb = (const float*)d_in[2];
    const float* user_mlp_w = (const float*)d_in[3];
    const float* user_mlp_b = (const float*)d_in[4];
    const float* gat1_w = (const float*)d_in[5];
    const float* lin1_w = (const float*)d_in[6];
    const float* lin1_b = (const float*)d_in[7];
    const float* g1_w = (const float*)d_in[8];
    const float* g1_b = (const float*)d_in[9];
    const float* gat2_w = (const float*)d_in[10];
    const float* lin2_w = (const float*)d_in[11];
    const float* lin2_b = (const float*)d_in[12];
    const float* g2_w = (const float*)d_in[13];
    const float* g2_b = (const float*)d_in[14];
    const int* edge_index = (const int*)d_in[15];
    float* out = (float*)d_out;

    int E = in_sizes[15] / 2;
    if (E > EE) E = EE;
    const int* src = edge_index;
    const int* dst = edge_index + E;

    float *p_x, *p_xw, *p_h, *p_xhat, *p_xcur;
    cudaGetSymbolAddress((void**)&p_x, g_x);
    cudaGetSymbolAddress((void**)&p_xw, g_xw);
    cudaGetSymbolAddress((void**)&p_h, g_h);
    cudaGetSymbolAddress((void**)&p_xhat, g_xhat);
    cudaGetSymbolAddress((void**)&p_xcur, g_xcur);

    int gn = (NN + 255) / 256;
    int ge = (E + 255) / 256;
    int nb = (NN + 1023) / 1024;
    const int GT = (NN + 127) / 128;
    const int AGB = NN / 4 / 8;   // 4 nodes/warp, 8 warps/block -> 3125 blocks

    static cudaStream_t sB = nullptr;
    static cudaEvent_t eFork = nullptr, eBuild = nullptr, eJoin = nullptr;
    static cudaEvent_t eLin1 = nullptr, eF1 = nullptr, eLin2 = nullptr;
    if (sB == nullptr) {
        cudaStreamCreateWithFlags(&sB, cudaStreamNonBlocking);
        cudaEventCreateWithFlags(&eFork, cudaEventDisableTiming);
        cudaEventCreateWithFlags(&eBuild, cudaEventDisableTiming);
        cudaEventCreateWithFlags(&eJoin, cudaEventDisableTiming);
        cudaEventCreateWithFlags(&eLin1, cudaEventDisableTiming);
        cudaEventCreateWithFlags(&eF1, cudaEventDisableTiming);
        cudaEventCreateWithFlags(&eLin2, cudaEventDisableTiming);
    }

    // fork
    cudaEventRecord(eFork, 0);
    cudaStreamWaitEvent(sB, eFork, 0);

    // sB: zero -> hist -> scan -> scatter -> lin1 (after eBuild)
    // s0: build -> gat1 -> (wait eJoin) agg1 -> (wait eLin1) final1 -> ...
    k_zero<<<gn, 256, 0, sB>>>();                                        // 1
    k_build<<<ITEM_B + USER_B, 256>>>(features, user_features,           // 2
                                      user_mlp_w, user_mlp_b);
    cudaEventRecord(eBuild, 0);
    k_hist<<<ge, 256, 0, sB>>>(src, dst, E);                             // 3
    k_gat<<<GT, 128>>>(p_x, gat1_w, p_xw, NN);                           // 4 (profiled)
    k_scan1<<<nb, 1024, 0, sB>>>();                                      // 5
    k_scan23<<<nb, 1024, 0, sB>>>(nb);                                   // 6
    k_scatter<<<ge, 256, 0, sB>>>(src, dst, E);                          // 7
    cudaEventRecord(eJoin, sB);
    cudaStreamWaitEvent(sB, eBuild, 0);
    k_lin<<<GT, 128, 0, sB>>>(p_x, lin1_w, lin1_b, id_emb, p_xhat, NN);  // 8
    cudaEventRecord(eLin1, sB);

    cudaStreamWaitEvent(0, eJoin, 0);
    k_agg<<<AGB, 256>>>();                                               // 9
    cudaStreamWaitEvent(0, eLin1, 0);
    k_final<<<GT, 128>>>(p_h, g1_w, g1_b, p_xhat, p_xcur, out, 1, NN);   // 10
    cudaEventRecord(eF1, 0);

    // hop 2: lin2 on sB concurrent with gat2+agg2 on s0
    cudaStreamWaitEvent(sB, eF1, 0);
    k_lin<<<GT, 128, 0, sB>>>(p_xcur, lin2_w, lin2_b, id_emb, p_xhat, NN);  // 11
    cudaEventRecord(eLin2, sB);

    k_gat<<<GT, 128>>>(p_xcur, gat2_w, p_xw, NN);                        // 12
    k_agg<<<AGB, 256>>>();                                               // 13
    cudaStreamWaitEvent(0, eLin2, 0);
    k_final<<<GT, 128>>>(p_h, g2_w, g2_b, p_xhat, p_x, out + 64, 0, NN); // 14
}